// round 13
// baseline (speedup 1.0000x reference)
#include <cuda_runtime.h>
#include <cuda_bf16.h>
#include <cstdint>

#define Bdim 2
#define Tdim 1024
#define Edim 1024
#define Hdim 16
#define Ddim 64
#define Rdim 32
#define Mdim (Bdim*Tdim)
#define CH 16
#define NC 16
#define CHK (Tdim/NC)

typedef unsigned long long ull;

// ---------------- scratch ----------------
__device__ float g_proj[(size_t)Mdim*5*Edim];
__device__ float g_gate[(size_t)Mdim*Edim];
__device__ float g_wdec[(size_t)Mdim*Edim];
__device__ float g_vr  [(size_t)Mdim*Hdim];
__device__ float g_rwkv[(size_t)Mdim*Edim];
__device__ float g_wcum[(size_t)Mdim*Edim];
__device__ float g_send[(size_t)Bdim*Hdim*NC*4096];
__device__ float g_sstart[(size_t)Bdim*Hdim*NC*4096];
__device__ float g_wprod[(size_t)Bdim*Hdim*NC*64];
__device__ float g_lbb [(size_t)6*Edim];
__device__ __align__(16) __nv_bfloat16 g_hdnh[(size_t)Mdim*6*Rdim];
__device__ __align__(16) __nv_bfloat16 g_hdnl[(size_t)Mdim*6*Rdim];
__device__ __align__(16) __nv_bfloat16 g_bwth[(size_t)6*Edim*Rdim];
__device__ __align__(16) __nv_bfloat16 g_bwtl[(size_t)6*Edim*Rdim];
__device__ __align__(16) __nv_bfloat16 g_ddh[(size_t)Mdim*5*Edim];
__device__ __align__(16) __nv_bfloat16 g_ddl[(size_t)Mdim*5*Edim];
__device__ __align__(16) __nv_bfloat16 g_gah[(size_t)Mdim*Edim];
__device__ __align__(16) __nv_bfloat16 g_gal[(size_t)Mdim*Edim];
__device__ __align__(16) __nv_bfloat16 g_oah[(size_t)Mdim*Edim];
__device__ __align__(16) __nv_bfloat16 g_oal[(size_t)Mdim*Edim];
__device__ __align__(16) __nv_bfloat16 g_gwt_h[(size_t)Edim*Edim];
__device__ __align__(16) __nv_bfloat16 g_gwt_l[(size_t)Edim*Edim];
__device__ __align__(16) __nv_bfloat16 g_owt_h[(size_t)Edim*Edim];
__device__ __align__(16) __nv_bfloat16 g_owt_l[(size_t)Edim*Edim];
__device__ __align__(16) __nv_bfloat16 g_mhd_h[(size_t)80*4096];
__device__ __align__(16) __nv_bfloat16 g_mhd_l[(size_t)80*4096];

// ---------------- helpers ----------------
__device__ __forceinline__ ull pack2(float lo, float hi){
    ull r; asm("mov.b64 %0, {%1, %2};" : "=l"(r) : "f"(lo), "f"(hi)); return r;
}
__device__ __forceinline__ void fma2(ull& d, ull a, ull b){
    asm("fma.rn.f32x2 %0, %1, %2, %3;" : "=l"(d) : "l"(a), "l"(b), "l"(d));
}
__device__ __forceinline__ void mul2(ull& d, ull a, ull b){
    asm("mul.rn.f32x2 %0, %1, %2;" : "=l"(d) : "l"(a), "l"(b));
}
__device__ __forceinline__ float2 unpack2(ull v){
    float lo, hi; asm("mov.b64 {%0, %1}, %2;" : "=f"(lo), "=f"(hi) : "l"(v));
    return make_float2(lo, hi);
}
__device__ __forceinline__ uint32_t smem_u32(const void* p){
    uint32_t a; asm("{ .reg .u64 t; cvta.to.shared.u64 t, %1; cvt.u32.u64 %0, t; }" : "=r"(a) : "l"(p));
    return a;
}
#define SW128(o) ((o) ^ ((((uint32_t)(o))>>3) & 0x70u))

#define LDSM4(r, addr) \
    asm volatile("ldmatrix.sync.aligned.m8n8.x4.shared.b16 {%0,%1,%2,%3}, [%4];" \
        : "=r"((r)[0]), "=r"((r)[1]), "=r"((r)[2]), "=r"((r)[3]) : "r"(addr))

#define MMA_BF16(c, a, b0, b1) \
    asm volatile("mma.sync.aligned.m16n8k16.row.col.f32.bf16.bf16.f32 " \
        "{%0,%1,%2,%3}, {%4,%5,%6,%7}, {%8,%9}, {%0,%1,%2,%3};" \
        : "+f"((c)[0]), "+f"((c)[1]), "+f"((c)[2]), "+f"((c)[3]) \
        : "r"((a)[0]), "r"((a)[1]), "r"((a)[2]), "r"((a)[3]), "r"(b0), "r"(b1))

// ---------------- K0: transpose + bf16-split E x E weights ----------------
__global__ __launch_bounds__(256) void k_wprep(const float* __restrict__ gw,
                                               const float* __restrict__ ow){
    __shared__ float tile[32][33];
    const float* src = blockIdx.z ? ow : gw;
    __nv_bfloat16* dh = blockIdx.z ? g_owt_h : g_gwt_h;
    __nv_bfloat16* dl = blockIdx.z ? g_owt_l : g_gwt_l;
    int k0 = blockIdx.x*32, n0 = blockIdx.y*32;
    int tid = threadIdx.x;
    int r = tid>>3, c = (tid&7)*4;
    float4 v4 = *(const float4*)&src[(size_t)(k0+r)*Edim + n0 + c];
    tile[r][c+0] = v4.x; tile[r][c+1] = v4.y;
    tile[r][c+2] = v4.z; tile[r][c+3] = v4.w;
    __syncthreads();
    #pragma unroll
    for (int j=0;j<4;j++){
        float v = tile[c+j][r];
        __nv_bfloat16 hi = __float2bfloat16(v);
        __nv_bfloat16 lo = __float2bfloat16(v - __bfloat162float(hi));
        size_t di = (size_t)(n0+r)*Edim + k0 + c + j;
        dh[di] = hi; dl[di] = lo;
    }
}

// ---------------- K0b: transpose + split per-head weights ----------------
__global__ __launch_bounds__(256) void k_mhdprep(const float* __restrict__ mhd){
    __shared__ float tile[64][68];
    int u = blockIdx.x;
    int tid = threadIdx.x;
    int row = tid>>2, c0 = (tid&3)*16;
    const float* src = mhd + (size_t)u*4096;
    #pragma unroll
    for (int j=0;j<4;j++)
        *(float4*)&tile[row][c0+j*4] = *(const float4*)&src[row*64 + c0 + j*4];
    __syncthreads();
    #pragma unroll
    for (int j=0;j<16;j++){
        float v = tile[c0+j][row];
        __nv_bfloat16 hi = __float2bfloat16(v);
        __nv_bfloat16 lo = __float2bfloat16(v - __bfloat162float(hi));
        size_t di = (size_t)u*4096 + row*64 + c0 + j;
        g_mhd_h[di] = hi; g_mhd_l[di] = lo;
    }
}

// ---------------- K0c: Bw[g][r][e] -> bwt[g][e][r] bf16 hi/lo; lbb = lam+Bb ----------------
__global__ __launch_bounds__(256) void k_bwprep(const float* __restrict__ Bw,
                                                const float* __restrict__ lam,
                                                const float* __restrict__ Bb){
    int g = blockIdx.y;
    int e = blockIdx.x*256 + threadIdx.x;
    __nv_bfloat16 hib[32], lob[32];
    #pragma unroll
    for (int r=0;r<32;r++){
        float v = Bw[((size_t)g*Rdim + r)*Edim + e];
        __nv_bfloat16 hi = __float2bfloat16(v);
        hib[r] = hi;
        lob[r] = __float2bfloat16(v - __bfloat162float(hi));
    }
    size_t db = ((size_t)g*Edim + e)*Rdim;
    #pragma unroll
    for (int j=0;j<4;j++){
        *(uint4*)&g_bwth[db + j*8] = *(uint4*)&hib[j*8];
        *(uint4*)&g_bwtl[db + j*8] = *(uint4*)&lob[j*8];
    }
    g_lbb[g*Edim + e] = lam[g*Edim + e] + Bb[g*Edim + e];
}

// ---------------- K1: hdn = tanh(z @ Aw[g] + Ab[g]) -> bf16 hi/lo ----------------
__global__ __launch_bounds__(256) void k_loraA(const float* __restrict__ x,
                                               const float* __restrict__ mu_x,
                                               const float* __restrict__ Aw,
                                               const float* __restrict__ Ab){
    __shared__ float zsm[64][36];
    __shared__ float wsmT[32][34];
    int g  = blockIdx.y;
    int m0 = blockIdx.x*64;
    int tid = threadIdx.x;
    int n = tid & 31, ty = tid >> 5;
    ull acc2[8];
    #pragma unroll
    for (int i=0;i<8;i++) acc2[i]=0ull;
    const float* wbase = Aw + (size_t)g*Edim*Rdim;
    for (int k0=0;k0<Edim;k0+=32){
        #pragma unroll
        for (int j=0;j<2;j++){
            int f = tid + j*256;
            int row = f>>3, c4 = (f&7)*4;
            int m = m0 + row;
            float4 xv = *(const float4*)&x[(size_t)m*Edim + k0 + c4];
            float4 lx = make_float4(0.f,0.f,0.f,0.f);
            if (m & (Tdim-1)) lx = *(const float4*)&x[(size_t)(m-1)*Edim + k0 + c4];
            float4 mu = *(const float4*)&mu_x[k0 + c4];
            float4 z;
            { float d=lx.x-xv.x; z.x = xv.x + d*(xv.x + d*mu.x); }
            { float d=lx.y-xv.y; z.y = xv.y + d*(xv.y + d*mu.y); }
            { float d=lx.z-xv.z; z.z = xv.z + d*(xv.z + d*mu.z); }
            { float d=lx.w-xv.w; z.w = xv.w + d*(xv.w + d*mu.w); }
            *(float4*)&zsm[row][c4] = z;
        }
        {
            int kk = tid>>3, r4 = (tid&7)*4;
            float4 wv = *(const float4*)&wbase[(size_t)(k0+kk)*Rdim + r4];
            wsmT[r4+0][kk] = wv.x; wsmT[r4+1][kk] = wv.y;
            wsmT[r4+2][kk] = wv.z; wsmT[r4+3][kk] = wv.w;
        }
        __syncthreads();
        #pragma unroll
        for (int kk2=0;kk2<16;kk2++){
            ull b2 = *(const ull*)&wsmT[n][2*kk2];
            #pragma unroll
            for (int i=0;i<8;i++){
                ull a2 = *(const ull*)&zsm[ty*8+i][2*kk2];
                fma2(acc2[i], a2, b2);
            }
        }
        __syncthreads();
    }
    float bias = Ab[g*Rdim + n];
    #pragma unroll
    for (int i=0;i<8;i++){
        float2 p = unpack2(acc2[i]);
        float v = tanhf(p.x + p.y + bias);
        __nv_bfloat16 hi = __float2bfloat16(v);
        size_t di = ((size_t)(m0+ty*8+i)*6 + g)*Rdim + n;
        g_hdnh[di] = hi;
        g_hdnl[di] = __float2bfloat16(v - __bfloat162float(hi));
    }
}

// ---------------- K2: loraB via HMMA + fused ddlerp epilogue ----------------
// grid (Mdim/128, Edim/128, 6). acc = hdn @ bwt^T (3-product split), then
// dd = x + (lx-x)*(acc + lbb) -> bf16 hi/lo.
#define LB_BUF 16384
#define LB_SMEM (4*LB_BUF + 1024)
__global__ __launch_bounds__(256)
void k_loraB_hmma(const float* __restrict__ x){
    extern __shared__ char smg[];
    uint32_t dynb = smem_u32(smg);
    uint32_t db = (dynb + 1023u) & ~1023u;
    char* dptr = smg + (db - dynb);
    int tid = threadIdx.x, wid = tid>>5, lane = tid&31;
    int g = blockIdx.z;
    int mBase = blockIdx.x*128, eBase = blockIdx.y*128;
    int wm = (wid&1)*64, wn = (wid>>1)*32;
    uint32_t sAh = db, sAl = db + LB_BUF, sBh = db + 2*LB_BUF, sBl = db + 3*LB_BUF;

    // load A (hdn, 128 rows x 32 bf16 = 64B/row, in 128B-padded rows) and B (bwt)
    #pragma unroll
    for (int k=0;k<2;k++){
        int idx = tid + k*256;          // 512 chunks: row=idx>>2, c=idx&3
        int row = idx>>2, c = idx&3;
        uint32_t swo = SW128((uint32_t)(row*128 + c*16));
        size_t ai = ((size_t)(mBase+row)*6 + g)*Rdim + c*8;
        *(uint4*)(dptr + swo)            = *(const uint4*)&g_hdnh[ai];
        *(uint4*)(dptr + LB_BUF + swo)   = *(const uint4*)&g_hdnl[ai];
        size_t bi = ((size_t)g*Edim + eBase+row)*Rdim + c*8;
        *(uint4*)(dptr + 2*LB_BUF + swo) = *(const uint4*)&g_bwth[bi];
        *(uint4*)(dptr + 3*LB_BUF + swo) = *(const uint4*)&g_bwtl[bi];
    }
    __syncthreads();

    float acc[4][4][4];
    #pragma unroll
    for (int mt=0;mt<4;mt++)
        #pragma unroll
        for (int nt=0;nt<4;nt++)
            #pragma unroll
            for (int j=0;j<4;j++) acc[mt][nt][j]=0.f;

    #pragma unroll
    for (int ks=0;ks<2;ks++){
        uint32_t ah[4][4], al[4][4];
        #pragma unroll
        for (int mt=0;mt<4;mt++){
            uint32_t off = SW128((uint32_t)((wm+mt*16+(lane&15))*128 + ks*32 + (lane>>4)*16));
            LDSM4(ah[mt], sAh + off);
            LDSM4(al[mt], sAl + off);
        }
        uint32_t bh[2][4], bl[2][4];
        #pragma unroll
        for (int p=0;p<2;p++){
            int brow = wn + p*16 + ((lane>>4)&1)*8 + (lane&7);
            uint32_t off = SW128((uint32_t)(brow*128 + ks*32 + ((lane>>3)&1)*16));
            LDSM4(bh[p], sBh + off);
            LDSM4(bl[p], sBl + off);
        }
        #pragma unroll
        for (int mt=0;mt<4;mt++){
            #pragma unroll
            for (int nt=0;nt<4;nt++){
                int p = nt>>1, o = (nt&1)*2;
                MMA_BF16(acc[mt][nt], ah[mt], bh[p][o], bh[p][o+1]);
                MMA_BF16(acc[mt][nt], ah[mt], bl[p][o], bl[p][o+1]);
                MMA_BF16(acc[mt][nt], al[mt], bh[p][o], bh[p][o+1]);
            }
        }
    }
    int gr = lane>>2, gc = (lane&3)*2;
    #pragma unroll
    for (int mt=0;mt<4;mt++){
        #pragma unroll
        for (int nt=0;nt<4;nt++){
            int col = eBase + wn + nt*8 + gc;
            float2 b2 = *(const float2*)&g_lbb[g*Edim + col];
            #pragma unroll
            for (int half=0; half<2; half++){
                int row = mBase + wm + mt*16 + gr + half*8;
                size_t xi = (size_t)row*Edim + col;
                float2 xv = *(const float2*)&x[xi];
                float2 lx = make_float2(0.f, 0.f);
                if (row & (Tdim-1)) lx = *(const float2*)&x[xi - Edim];
                float a0 = acc[mt][nt][half*2]   + b2.x;
                float a1 = acc[mt][nt][half*2+1] + b2.y;
                float d0 = xv.x + (lx.x - xv.x)*a0;
                float d1 = xv.y + (lx.y - xv.y)*a1;
                __nv_bfloat16 h0 = __float2bfloat16(d0);
                __nv_bfloat16 h1 = __float2bfloat16(d1);
                __nv_bfloat16 l0 = __float2bfloat16(d0 - __bfloat162float(h0));
                __nv_bfloat16 l1 = __float2bfloat16(d1 - __bfloat162float(h1));
                __nv_bfloat162 hp; hp.x = h0; hp.y = h1;
                __nv_bfloat162 lp; lp.x = l0; lp.y = l1;
                if (g == 5){
                    *(__nv_bfloat162*)&g_gah[xi] = hp;
                    *(__nv_bfloat162*)&g_gal[xi] = lp;
                } else {
                    size_t di = ((size_t)row*5 + g)*Edim + col;
                    *(__nv_bfloat162*)&g_ddh[di] = hp;
                    *(__nv_bfloat162*)&g_ddl[di] = lp;
                }
            }
        }
    }
}

// ---------------- K3: per-head 64x64 GEMM via HMMA bf16-split ----------------
#define PH_SMEM 49152
__global__ __launch_bounds__(256)
void k_headgemm(const float* __restrict__ unused){
    extern __shared__ char smg[];
    uint32_t dynb = smem_u32(smg);
    uint32_t db = (dynb + 1023u) & ~1023u;
    char* dptr = smg + (db - dynb);
    int tid = threadIdx.x, wid = tid>>5, lane = tid&31;
    int u = blockIdx.y;
    int g = u>>4, h = u&15;
    int mBase = blockIdx.x*128;
    int wm = (wid&3)*32, wn = (wid>>2)*32;
    uint32_t sAh = db, sAl = db + 16384, sBh = db + 32768, sBl = db + 40960;
    #pragma unroll
    for (int k=0;k<4;k++){
        int idx = tid + k*256;
        int row = idx>>3, c = idx&7;
        size_t si = ((size_t)(mBase+row)*5 + g)*Edim + h*64 + c*8;
        uint32_t swo = SW128((uint32_t)(row*128 + c*16));
        *(uint4*)(dptr + swo)          = *(const uint4*)&g_ddh[si];
        *(uint4*)(dptr + 16384 + swo)  = *(const uint4*)&g_ddl[si];
    }
    #pragma unroll
    for (int k=0;k<2;k++){
        int idx = tid + k*256;
        int row = idx>>3, c = idx&7;
        size_t si = (size_t)u*4096 + row*64 + c*8;
        uint32_t swo = SW128((uint32_t)(row*128 + c*16));
        *(uint4*)(dptr + 32768 + swo)  = *(const uint4*)&g_mhd_h[si];
        *(uint4*)(dptr + 40960 + swo)  = *(const uint4*)&g_mhd_l[si];
    }
    __syncthreads();
    float acc[2][4][4];
    #pragma unroll
    for (int mt=0;mt<2;mt++)
        #pragma unroll
        for (int nt=0;nt<4;nt++)
            #pragma unroll
            for (int j=0;j<4;j++) acc[mt][nt][j]=0.f;
    #pragma unroll
    for (int ks=0;ks<4;ks++){
        uint32_t ah[2][4], al[2][4];
        #pragma unroll
        for (int mt=0;mt<2;mt++){
            uint32_t off = SW128((uint32_t)((wm+mt*16+(lane&15))*128 + ks*32 + (lane>>4)*16));
            LDSM4(ah[mt], sAh + off);
            LDSM4(al[mt], sAl + off);
        }
        uint32_t bh[2][4], bl[2][4];
        #pragma unroll
        for (int p=0;p<2;p++){
            int brow = wn + p*16 + ((lane>>4)&1)*8 + (lane&7);
            uint32_t off = SW128((uint32_t)(brow*128 + ks*32 + ((lane>>3)&1)*16));
            LDSM4(bh[p], sBh + off);
            LDSM4(bl[p], sBl + off);
        }
        #pragma unroll
        for (int mt=0;mt<2;mt++){
            #pragma unroll
            for (int nt=0;nt<4;nt++){
                int p = nt>>1, o = (nt&1)*2;
                MMA_BF16(acc[mt][nt], ah[mt], bh[p][o], bh[p][o+1]);
                MMA_BF16(acc[mt][nt], ah[mt], bl[p][o], bl[p][o+1]);
                MMA_BF16(acc[mt][nt], al[mt], bh[p][o], bh[p][o+1]);
            }
        }
    }
    int gr = lane>>2, gc = (lane&3)*2;
    #pragma unroll
    for (int mt=0;mt<2;mt++){
        #pragma unroll
        for (int nt=0;nt<4;nt++){
            int row = mBase + wm + mt*16 + gr;
            int col = h*64 + wn + nt*8 + gc;
            size_t o0 = (size_t)row*5*Edim + (size_t)g*Edim + col;
            size_t o1 = (size_t)(row+8)*5*Edim + (size_t)g*Edim + col;
            *(float2*)&g_proj[o0] = make_float2(acc[mt][nt][0], acc[mt][nt][1]);
            *(float2*)&g_proj[o1] = make_float2(acc[mt][nt][2], acc[mt][nt][3]);
        }
    }
}

// ---------------- K3b: fused decay lora + parallel vr ----------------
__global__ __launch_bounds__(256) void k_wdecay(const float* __restrict__ wlam,
                                                const float* __restrict__ wA,
                                                const float* __restrict__ wB){
    __shared__ float asm_[64][68];
    __shared__ float wsm[64][68];
    int h = blockIdx.y;
    int m0 = blockIdx.x*64;
    int tid = threadIdx.x;
    {
        int row = tid>>2, q = tid&3;
        const float* v = g_proj + ((size_t)(m0+row)*5+1)*Edim + h*64 + q*16;
        const float* r = g_proj + ((size_t)(m0+row)*5+2)*Edim + h*64 + q*16;
        float s = 0.f;
        #pragma unroll
        for (int j=0;j<4;j++){
            float4 vv = *(const float4*)&v[j*4];
            float4 rr = *(const float4*)&r[j*4];
            s += vv.x*rr.x + vv.y*rr.y + vv.z*rr.z + vv.w*rr.w;
        }
        s += __shfl_xor_sync(0xffffffffu, s, 1);
        s += __shfl_xor_sync(0xffffffffu, s, 2);
        if (q==0) g_vr[(m0+row)*Hdim + h] = s;
    }
    #pragma unroll
    for (int j=0;j<4;j++){
        int f = tid + j*256;
        int row = f>>4, c4 = (f&15)*4;
        *(float4*)&asm_[row][c4] =
            *(const float4*)&g_proj[(size_t)(m0+row)*5*Edim + 3*Edim + h*64 + c4];
        *(float4*)&wsm[row][c4] = *(const float4*)&wA[(size_t)h*4096 + row*64 + c4];
    }
    __syncthreads();
    int tx = tid&15, ty = tid>>4;
    int n0 = tx*4, m0r = ty*4;
    ull acc[4][2];
    #pragma unroll
    for (int i=0;i<4;i++){ acc[i][0]=0ull; acc[i][1]=0ull; }
    #pragma unroll 16
    for (int k=0;k<64;k++){
        ull b01 = *(const ull*)&wsm[k][n0];
        ull b23 = *(const ull*)&wsm[k][n0+2];
        #pragma unroll
        for (int i=0;i<4;i++){
            float a = asm_[m0r+i][k];
            ull a2 = pack2(a, a);
            fma2(acc[i][0], a2, b01);
            fma2(acc[i][1], a2, b23);
        }
    }
    __syncthreads();
    #pragma unroll
    for (int i=0;i<4;i++){
        float2 lo = unpack2(acc[i][0]), hi = unpack2(acc[i][1]);
        *(float4*)&asm_[m0r+i][n0] =
            make_float4(tanhf(lo.x), tanhf(lo.y), tanhf(hi.x), tanhf(hi.y));
        acc[i][0]=0ull; acc[i][1]=0ull;
    }
    #pragma unroll
    for (int j=0;j<4;j++){
        int f = tid + j*256;
        int row = f>>4, c4 = (f&15)*4;
        *(float4*)&wsm[row][c4] = *(const float4*)&wB[(size_t)h*4096 + row*64 + c4];
    }
    __syncthreads();
    #pragma unroll 16
    for (int k=0;k<64;k++){
        ull b01 = *(const ull*)&wsm[k][n0];
        ull b23 = *(const ull*)&wsm[k][n0+2];
        #pragma unroll
        for (int i=0;i<4;i++){
            float a = asm_[m0r+i][k];
            ull a2 = pack2(a, a);
            fma2(acc[i][0], a2, b01);
            fma2(acc[i][1], a2, b23);
        }
    }
    #pragma unroll
    for (int i=0;i<4;i++){
        float2 lo = unpack2(acc[i][0]), hi = unpack2(acc[i][1]);
        float v[4] = {lo.x, lo.y, hi.x, hi.y};
        #pragma unroll
        for (int j=0;j<4;j++)
            v[j] = expf(-expf(v[j] + wlam[h*64 + n0 + j]));
        *(float4*)&g_wdec[(size_t)(m0+m0r+i)*Edim + h*64 + n0] =
            make_float4(v[0],v[1],v[2],v[3]);
    }
}

// ---------------- K4: HMMA bf16-split big GEMM ----------------
#define HS_BUF 16384
#define HS_SMEM (4*HS_BUF + 1024)
__global__ __launch_bounds__(256)
void k_gemm_hmma(const __nv_bfloat16* __restrict__ Ah, const __nv_bfloat16* __restrict__ Al,
                 const __nv_bfloat16* __restrict__ Bh, const __nv_bfloat16* __restrict__ Bl,
                 const float* __restrict__ bias, float* __restrict__ C){
    extern __shared__ char smg[];
    uint32_t dynb = smem_u32(smg);
    uint32_t db = (dynb + 1023u) & ~1023u;
    char* dptr = smg + (db - dynb);
    int tid = threadIdx.x, wid = tid>>5, lane = tid&31;
    int mBase = blockIdx.x*128, nBase = blockIdx.y*128;
    int wm = (wid&1)*64, wn = (wid>>1)*32;
    uint32_t sAh = db, sAl = db + HS_BUF, sBh = db + 2*HS_BUF, sBl = db + 3*HS_BUF;
    float acc[4][4][4];
    #pragma unroll
    for (int mt=0;mt<4;mt++)
        #pragma unroll
        for (int nt=0;nt<4;nt++)
            #pragma unroll
            for (int j=0;j<4;j++) acc[mt][nt][j]=0.f;
    int lrow = tid>>3, lc = tid&7;
    uint4 pa[4], pal[4], pb[4], pbl[4];
    #pragma unroll
    for (int jj=0;jj<4;jj++){
        int row = lrow + jj*32;
        pa[jj]  = *(const uint4*)&Ah[(size_t)(mBase+row)*Edim + lc*8];
        pal[jj] = *(const uint4*)&Al[(size_t)(mBase+row)*Edim + lc*8];
        pb[jj]  = *(const uint4*)&Bh[(size_t)(nBase+row)*Edim + lc*8];
        pbl[jj] = *(const uint4*)&Bl[(size_t)(nBase+row)*Edim + lc*8];
    }
    for (int i=0;i<16;i++){
        #pragma unroll
        for (int jj=0;jj<4;jj++){
            int row = lrow + jj*32;
            uint32_t swo = SW128((uint32_t)(row*128 + lc*16));
            *(uint4*)(dptr + swo)            = pa[jj];
            *(uint4*)(dptr + HS_BUF + swo)   = pal[jj];
            *(uint4*)(dptr + 2*HS_BUF + swo) = pb[jj];
            *(uint4*)(dptr + 3*HS_BUF + swo) = pbl[jj];
        }
        __syncthreads();
        if (i+1 < 16){
            int k0 = (i+1)*64;
            #pragma unroll
            for (int jj=0;jj<4;jj++){
                int row = lrow + jj*32;
                pa[jj]  = *(const uint4*)&Ah[(size_t)(mBase+row)*Edim + k0 + lc*8];
                pal[jj] = *(const uint4*)&Al[(size_t)(mBase+row)*Edim + k0 + lc*8];
                pb[jj]  = *(const uint4*)&Bh[(size_t)(nBase+row)*Edim + k0 + lc*8];
                pbl[jj] = *(const uint4*)&Bl[(size_t)(nBase+row)*Edim + k0 + lc*8];
            }
        }
        #pragma unroll
        for (int ks=0;ks<4;ks++){
            uint32_t ah[4][4], al[4][4];
            #pragma unroll
            for (int mt=0;mt<4;mt++){
                uint32_t off = SW128((uint32_t)((wm+mt*16+(lane&15))*128 + ks*32 + (lane>>4)*16));
                LDSM4(ah[mt], sAh + off);
                LDSM4(al[mt], sAl + off);
            }
            uint32_t bh[2][4], bl[2][4];
            #pragma unroll
            for (int p=0;p<2;p++){
                int brow = wn + p*16 + ((lane>>4)&1)*8 + (lane&7);
                uint32_t off = SW128((uint32_t)(brow*128 + ks*32 + ((lane>>3)&1)*16));
                LDSM4(bh[p], sBh + off);
                LDSM4(bl[p], sBl + off);
            }
            #pragma unroll
            for (int mt=0;mt<4;mt++){
                #pragma unroll
                for (int nt=0;nt<4;nt++){
                    int p = nt>>1, o = (nt&1)*2;
                    MMA_BF16(acc[mt][nt], ah[mt], bh[p][o], bh[p][o+1]);
                    MMA_BF16(acc[mt][nt], ah[mt], bl[p][o], bl[p][o+1]);
                    MMA_BF16(acc[mt][nt], al[mt], bh[p][o], bh[p][o+1]);
                }
            }
        }
        __syncthreads();
    }
    int gr = lane>>2, gc = (lane&3)*2;
    #pragma unroll
    for (int mt=0;mt<4;mt++){
        #pragma unroll
        for (int nt=0;nt<4;nt++){
            int row = mBase + wm + mt*16 + gr;
            int col = nBase + wn + nt*8 + gc;
            float b0 = bias ? bias[col] : 0.f;
            float b1 = bias ? bias[col+1] : 0.f;
            *(float2*)&C[(size_t)row*Edim + col] =
                make_float2(acc[mt][nt][0] + b0, acc[mt][nt][1] + b1);
            *(float2*)&C[(size_t)(row+8)*Edim + col] =
                make_float2(acc[mt][nt][2] + b0, acc[mt][nt][3] + b1);
        }
    }
}

// ---------------- K6a: chunk-local recurrence ----------------
__global__ __launch_bounds__(256) void k_recur1(){
    int unit = blockIdx.x;
    int c = unit & (NC-1);
    int bh = unit >> 4;
    int b = bh >> 4, h = bh & 15;
    int tid = threadIdx.x;
    int row = tid >> 2, q = tid & 3, c0 = q*16;
    __shared__ float sk[CH][64], su[CH][64], sw[CH][64], sv[CH][64], sr[CH][64];
    __shared__ float svr[CH], sout[CH][64], swcum[CH][64];
    ull S2[8];
    #pragma unroll
    for (int j=0;j<8;j++) S2[j] = 0ull;
    float wcumr = 1.f;
    int mbase = b*Tdim + c*CHK;
    float rk[4], ru[4], rw[4], rv[4], rr[4], rvr = 0.f;
    #pragma unroll
    for (int it=0;it<4;it++){
        int idx = tid + it*256; int st = idx>>6, col = idx&63;
        size_t m = (size_t)(mbase + st);
        const float* bp = g_proj + m*5*Edim + h*64 + col;
        rk[it] = bp[0]; rv[it] = bp[Edim]; rr[it] = bp[2*Edim]; ru[it] = bp[4*Edim];
        rw[it] = g_wdec[m*Edim + h*64 + col];
    }
    if (tid < CH) rvr = g_vr[(mbase+tid)*Hdim + h];
    for (int cc=0; cc<CHK/CH; cc++){
        #pragma unroll
        for (int it=0;it<4;it++){
            int idx = tid + it*256; int st = idx>>6, col = idx&63;
            sk[st][col]=rk[it]; su[st][col]=ru[it]; sw[st][col]=rw[it];
            sv[st][col]=rv[it]; sr[st][col]=rr[it];
        }
        if (tid < CH) svr[tid] = rvr;
        __syncthreads();
        if (cc+1 < CHK/CH){
            int t0 = (cc+1)*CH;
            #pragma unroll
            for (int it=0;it<4;it++){
                int idx = tid + it*256; int st = idx>>6, col = idx&63;
                size_t m = (size_t)(mbase + t0 + st);
                const float* bp = g_proj + m*5*Edim + h*64 + col;
                rk[it] = bp[0]; rv[it] = bp[Edim]; rr[it] = bp[2*Edim]; ru[it] = bp[4*Edim];
                rw[it] = g_wdec[m*Edim + h*64 + col];
            }
            if (tid < CH) rvr = g_vr[(mbase+t0+tid)*Hdim + h];
        }
        #pragma unroll
        for (int t=0;t<CH;t++){
            float kc = sk[t][row], wc = sw[t][row], uc = su[t][row], vc = svr[t];
            ull kc2 = pack2(kc, kc), wc2 = pack2(wc, wc);
            const ull* r2 = (const ull*)&sr[t][c0];
            const ull* v2 = (const ull*)&sv[t][c0];
            ull da0=0ull, da1=0ull, da2=0ull, da3=0ull;
            fma2(da0, S2[0], r2[0]); fma2(da1, S2[1], r2[1]);
            fma2(da2, S2[2], r2[2]); fma2(da3, S2[3], r2[3]);
            fma2(da0, S2[4], r2[4]); fma2(da1, S2[5], r2[5]);
            fma2(da2, S2[6], r2[6]); fma2(da3, S2[7], r2[7]);
            float2 p0 = unpack2(da0), p1 = unpack2(da1);
            float2 p2 = unpack2(da2), p3 = unpack2(da3);
            float dot = ((p0.x+p0.y)+(p1.x+p1.y)) + ((p2.x+p2.y)+(p3.x+p3.y));
            dot += __shfl_xor_sync(0xffffffffu, dot, 1);
            dot += __shfl_xor_sync(0xffffffffu, dot, 2);
            if (q==0){
                sout[t][row]  = uc*kc*vc + dot;
                swcum[t][row] = wcumr;
            }
            wcumr *= wc;
            #pragma unroll
            for (int j=0;j<8;j++){
                mul2(S2[j], wc2, S2[j]);
                fma2(S2[j], kc2, v2[j]);
            }
        }
        __syncthreads();
        #pragma unroll
        for (int it=0;it<4;it++){
            int idx = tid + it*256; int st = idx>>6, col = idx&63;
            size_t di = (size_t)(mbase + cc*CH + st)*Edim + h*64 + col;
            g_rwkv[di] = sout[st][col];
            g_wcum[di] = swcum[st][col];
        }
    }
    size_t sb = ((size_t)bh*NC + c)*4096 + row*64 + c0;
    #pragma unroll
    for (int j=0;j<8;j++)
        *(ull*)&g_send[sb + 2*j] = S2[j];
    if (q==0) g_wprod[((size_t)bh*NC + c)*64 + row] = wcumr;
}

// ---------------- K6b: sequential chunk combine ----------------
__global__ __launch_bounds__(256) void k_recur2(){
    int bh = blockIdx.x;
    int tid = threadIdx.x;
    int off = tid*16;
    int d = off >> 6;
    float4 S[4];
    #pragma unroll
    for (int j=0;j<4;j++) S[j] = make_float4(0.f,0.f,0.f,0.f);
    for (int c=0;c<NC;c++){
        size_t sb = ((size_t)bh*NC + c)*4096 + off;
        #pragma unroll
        for (int j=0;j<4;j++)
            *(float4*)&g_sstart[sb + j*4] = S[j];
        float wp = g_wprod[((size_t)bh*NC + c)*64 + d];
        #pragma unroll
        for (int j=0;j<4;j++){
            float4 se = *(const float4*)&g_send[sb + j*4];
            S[j].x = se.x + wp*S[j].x;
            S[j].y = se.y + wp*S[j].y;
            S[j].z = se.z + wp*S[j].z;
            S[j].w = se.w + wp*S[j].w;
        }
    }
}

// ---------------- K6c: cross-chunk correction ----------------
__global__ __launch_bounds__(256) void k_recur3(){
    __shared__ float rsm[64][68];
    __shared__ float ssm[64][68];
    int h = blockIdx.y;
    int m0 = blockIdx.x*64;
    int b = m0 >> 10;
    int c = (m0 & (Tdim-1)) >> 6;
    int bh = b*Hdim + h;
    const float* Sst = g_sstart + ((size_t)bh*NC + c)*4096;
    int tid = threadIdx.x;
    #pragma unroll
    for (int j=0;j<4;j++){
        int f = tid + j*256;
        int row = f>>4, c4 = (f&15)*4;
        *(float4*)&rsm[row][c4] =
            *(const float4*)&g_proj[(size_t)(m0+row)*5*Edim + 2*Edim + h*64 + c4];
        float4 sv = *(const float4*)&Sst[row*64 + c4];
        ssm[c4+0][row] = sv.x; ssm[c4+1][row] = sv.y;
        ssm[c4+2][row] = sv.z; ssm[c4+3][row] = sv.w;
    }
    __syncthreads();
    int tx = tid&15, ty = tid>>4;
    int n0 = tx*4, m0r = ty*4;
    ull acc[4][2];
    #pragma unroll
    for (int i=0;i<4;i++){ acc[i][0]=0ull; acc[i][1]=0ull; }
    #pragma unroll 16
    for (int k=0;k<64;k++){
        ull b01 = *(const ull*)&ssm[k][n0];
        ull b23 = *(const ull*)&ssm[k][n0+2];
        #pragma unroll
        for (int i=0;i<4;i++){
            float a = rsm[m0r+i][k];
            ull a2 = pack2(a, a);
            fma2(acc[i][0], a2, b01);
            fma2(acc[i][1], a2, b23);
        }
    }
    #pragma unroll
    for (int i=0;i<4;i++){
        float2 lo = unpack2(acc[i][0]), hi = unpack2(acc[i][1]);
        size_t di = (size_t)(m0+m0r+i)*Edim + h*64 + n0;
        float4 wc = *(const float4*)&g_wcum[di];
        float4 ov = *(const float4*)&g_rwkv[di];
        ov.x += wc.x*lo.x; ov.y += wc.y*lo.y;
        ov.z += wc.z*hi.x; ov.w += wc.w*hi.y;
        *(float4*)&g_rwkv[di] = ov;
    }
}

// ---------------- K7: GroupNorm * silu(gate) -> bf16 hi/lo ----------------
__global__ __launch_bounds__(256) void k_gn(const float* __restrict__ gamma,
                                            const float* __restrict__ beta){
    int unit = blockIdx.x*8 + (threadIdx.x>>5);
    int lane = threadIdx.x & 31;
    int m = unit>>4, h = unit&15;
    size_t base = (size_t)m*Edim + h*64;
    float v1 = g_rwkv[base + lane];
    float v2 = g_rwkv[base + 32 + lane];
    float s = v1+v2, sq = v1*v1 + v2*v2;
    #pragma unroll
    for (int o=16;o;o>>=1){
        s  += __shfl_xor_sync(0xffffffffu, s, o);
        sq += __shfl_xor_sync(0xffffffffu, sq, o);
    }
    float mean = s*(1.f/64.f);
    float var  = sq*(1.f/64.f) - mean*mean;
    float rstd = rsqrtf(var + 1e-3f);
    #pragma unroll
    for (int half=0; half<2; half++){
        int e = h*64 + half*32 + lane;
        float v = half ? v2 : v1;
        float nv = (v-mean)*rstd*gamma[e] + beta[e];
        float gg = g_gate[(size_t)m*Edim + e];
        float a = nv * (gg/(1.f+expf(-gg)));
        size_t di = (size_t)m*Edim + e;
        __nv_bfloat16 hi = __float2bfloat16(a);
        g_oah[di] = hi;
        g_oal[di] = __float2bfloat16(a - __bfloat162float(hi));
    }
}

extern "C" void kernel_launch(void* const* d_in, const int* in_sizes, int n_in,
                              void* d_out, int out_size) {
    const float* x    = (const float*)d_in[0];
    const float* mu_x = (const float*)d_in[1];
    const float* lam  = (const float*)d_in[2];
    const float* Aw   = (const float*)d_in[3];
    const float* Ab   = (const float*)d_in[4];
    const float* Bw   = (const float*)d_in[5];
    const float* Bb   = (const float*)d_in[6];
    const float* mhd  = (const float*)d_in[7];
    const float* gw   = (const float*)d_in[8];
    const float* wlam = (const float*)d_in[9];
    const float* wA   = (const float*)d_in[10];
    const float* wB   = (const float*)d_in[11];
    const float* gng  = (const float*)d_in[12];
    const float* gnb  = (const float*)d_in[13];
    const float* ow   = (const float*)d_in[14];
    const float* ob   = (const float*)d_in[15];
    float* out = (float*)d_out;

    float *p_gate;
    cudaGetSymbolAddress((void**)&p_gate, g_gate);
    __nv_bfloat16 *p_gah, *p_gal, *p_oah, *p_oal, *p_gwh, *p_gwl, *p_owh, *p_owl;
    cudaGetSymbolAddress((void**)&p_gah, g_gah);
    cudaGetSymbolAddress((void**)&p_gal, g_gal);
    cudaGetSymbolAddress((void**)&p_oah, g_oah);
    cudaGetSymbolAddress((void**)&p_oal, g_oal);
    cudaGetSymbolAddress((void**)&p_gwh, g_gwt_h);
    cudaGetSymbolAddress((void**)&p_gwl, g_gwt_l);
    cudaGetSymbolAddress((void**)&p_owh, g_owt_h);
    cudaGetSymbolAddress((void**)&p_owl, g_owt_l);

    static cudaStream_t s2 = nullptr;
    static cudaEvent_t e_lb = nullptr, e_gate = nullptr;
    static bool attr_done = false;
    if (!attr_done){
        cudaFuncSetAttribute(k_gemm_hmma,  cudaFuncAttributeMaxDynamicSharedMemorySize, HS_SMEM);
        cudaFuncSetAttribute(k_headgemm,   cudaFuncAttributeMaxDynamicSharedMemorySize, PH_SMEM + 1024);
        cudaFuncSetAttribute(k_loraB_hmma, cudaFuncAttributeMaxDynamicSharedMemorySize, LB_SMEM);
        cudaStreamCreateWithFlags(&s2, cudaStreamNonBlocking);
        cudaEventCreateWithFlags(&e_lb,   cudaEventDisableTiming);
        cudaEventCreateWithFlags(&e_gate, cudaEventDisableTiming);
        attr_done = true;
    }

    k_wprep<<<dim3(Edim/32, Edim/32, 2), 256>>>(gw, ow);
    k_mhdprep<<<80, 256>>>(mhd);
    k_bwprep<<<dim3(Edim/256, 6), 256>>>(Bw, lam, Bb);
    k_loraA<<<dim3(Mdim/64, 6), 256>>>(x, mu_x, Aw, Ab);
    k_loraB_hmma<<<dim3(Mdim/128, Edim/128, 6), 256, LB_SMEM>>>(x);
    cudaEventRecord(e_lb, 0);

    cudaStreamWaitEvent(s2, e_lb, 0);
    k_gemm_hmma<<<dim3(Mdim/128, Edim/128), 256, HS_SMEM, s2>>>(p_gah, p_gal, p_gwh, p_gwl, nullptr, p_gate);
    cudaEventRecord(e_gate, s2);

    k_headgemm<<<dim3(Mdim/128, 80), 256, PH_SMEM + 1024>>>(nullptr);
    k_wdecay<<<dim3(Mdim/64, 16), 256>>>(wlam, wA, wB);
    k_recur1<<<Bdim*Hdim*NC, 256>>>();
    k_recur2<<<Bdim*Hdim, 256>>>();
    k_recur3<<<dim3(Mdim/64, Hdim), 256>>>();
    cudaStreamWaitEvent(0, e_gate, 0);
    k_gn<<<(Mdim*Hdim)/8, 256>>>(gng, gnb);
    k_gemm_hmma<<<dim3(Mdim/128, Edim/128), 256, HS_SMEM>>>(p_oah, p_oal, p_owh, p_owl, ob, out);
}

// round 14
// speedup vs baseline: 1.1553x; 1.1553x over previous
#include <cuda_runtime.h>
#include <cuda_bf16.h>
#include <cstdint>

#define Bdim 2
#define Tdim 1024
#define Edim 1024
#define Hdim 16
#define Ddim 64
#define Rdim 32
#define Mdim (Bdim*Tdim)
#define CH 16
#define NC 16
#define CHK (Tdim/NC)
#define KSPLIT 4

typedef unsigned long long ull;

// ---------------- scratch ----------------
__device__ float g_hdn [(size_t)Mdim*6*Rdim];
__device__ float g_hdnp[(size_t)KSPLIT*Mdim*6*Rdim];
__device__ float g_proj[(size_t)Mdim*5*Edim];
__device__ float g_gate[(size_t)Mdim*Edim];
__device__ float g_wdec[(size_t)Mdim*Edim];
__device__ float g_vr  [(size_t)Mdim*Hdim];
__device__ float g_rwkv[(size_t)Mdim*Edim];
__device__ float g_wcum[(size_t)Mdim*Edim];
__device__ float g_send[(size_t)Bdim*Hdim*NC*4096];
__device__ float g_sstart[(size_t)Bdim*Hdim*NC*4096];
__device__ float g_wprod[(size_t)Bdim*Hdim*NC*64];
__device__ __align__(16) __nv_bfloat16 g_ddh[(size_t)Mdim*5*Edim];
__device__ __align__(16) __nv_bfloat16 g_ddl[(size_t)Mdim*5*Edim];
__device__ __align__(16) __nv_bfloat16 g_gah[(size_t)Mdim*Edim];
__device__ __align__(16) __nv_bfloat16 g_gal[(size_t)Mdim*Edim];
__device__ __align__(16) __nv_bfloat16 g_oah[(size_t)Mdim*Edim];
__device__ __align__(16) __nv_bfloat16 g_oal[(size_t)Mdim*Edim];
__device__ __align__(16) __nv_bfloat16 g_gwt_h[(size_t)Edim*Edim];
__device__ __align__(16) __nv_bfloat16 g_gwt_l[(size_t)Edim*Edim];
__device__ __align__(16) __nv_bfloat16 g_owt_h[(size_t)Edim*Edim];
__device__ __align__(16) __nv_bfloat16 g_owt_l[(size_t)Edim*Edim];
__device__ __align__(16) __nv_bfloat16 g_mhd_h[(size_t)80*4096];
__device__ __align__(16) __nv_bfloat16 g_mhd_l[(size_t)80*4096];

// ---------------- helpers ----------------
__device__ __forceinline__ ull pack2(float lo, float hi){
    ull r; asm("mov.b64 %0, {%1, %2};" : "=l"(r) : "f"(lo), "f"(hi)); return r;
}
__device__ __forceinline__ void fma2(ull& d, ull a, ull b){
    asm("fma.rn.f32x2 %0, %1, %2, %3;" : "=l"(d) : "l"(a), "l"(b), "l"(d));
}
__device__ __forceinline__ void mul2(ull& d, ull a, ull b){
    asm("mul.rn.f32x2 %0, %1, %2;" : "=l"(d) : "l"(a), "l"(b));
}
__device__ __forceinline__ float2 unpack2(ull v){
    float lo, hi; asm("mov.b64 {%0, %1}, %2;" : "=f"(lo), "=f"(hi) : "l"(v));
    return make_float2(lo, hi);
}
__device__ __forceinline__ uint32_t smem_u32(const void* p){
    uint32_t a; asm("{ .reg .u64 t; cvta.to.shared.u64 t, %1; cvt.u32.u64 %0, t; }" : "=r"(a) : "l"(p));
    return a;
}
#define SW128(o) ((o) ^ ((((uint32_t)(o))>>3) & 0x70u))

#define LDSM4(r, addr) \
    asm volatile("ldmatrix.sync.aligned.m8n8.x4.shared.b16 {%0,%1,%2,%3}, [%4];" \
        : "=r"((r)[0]), "=r"((r)[1]), "=r"((r)[2]), "=r"((r)[3]) : "r"(addr))

#define MMA_BF16(c, a, b0, b1) \
    asm volatile("mma.sync.aligned.m16n8k16.row.col.f32.bf16.bf16.f32 " \
        "{%0,%1,%2,%3}, {%4,%5,%6,%7}, {%8,%9}, {%0,%1,%2,%3};" \
        : "+f"((c)[0]), "+f"((c)[1]), "+f"((c)[2]), "+f"((c)[3]) \
        : "r"((a)[0]), "r"((a)[1]), "r"((a)[2]), "r"((a)[3]), "r"(b0), "r"(b1))

// ---------------- K0: transpose + bf16-split E x E weights ----------------
__global__ __launch_bounds__(256) void k_wprep(const float* __restrict__ gw,
                                               const float* __restrict__ ow){
    __shared__ float tile[32][33];
    const float* src = blockIdx.z ? ow : gw;
    __nv_bfloat16* dh = blockIdx.z ? g_owt_h : g_gwt_h;
    __nv_bfloat16* dl = blockIdx.z ? g_owt_l : g_gwt_l;
    int k0 = blockIdx.x*32, n0 = blockIdx.y*32;
    int tid = threadIdx.x;
    int r = tid>>3, c = (tid&7)*4;
    float4 v4 = *(const float4*)&src[(size_t)(k0+r)*Edim + n0 + c];
    tile[r][c+0] = v4.x; tile[r][c+1] = v4.y;
    tile[r][c+2] = v4.z; tile[r][c+3] = v4.w;
    __syncthreads();
    #pragma unroll
    for (int j=0;j<4;j++){
        float v = tile[c+j][r];
        __nv_bfloat16 hi = __float2bfloat16(v);
        __nv_bfloat16 lo = __float2bfloat16(v - __bfloat162float(hi));
        size_t di = (size_t)(n0+r)*Edim + k0 + c + j;
        dh[di] = hi; dl[di] = lo;
    }
}

// ---------------- K0b: transpose + split per-head weights ----------------
__global__ __launch_bounds__(256) void k_mhdprep(const float* __restrict__ mhd){
    __shared__ float tile[64][68];
    int u = blockIdx.x;
    int tid = threadIdx.x;
    int row = tid>>2, c0 = (tid&3)*16;
    const float* src = mhd + (size_t)u*4096;
    #pragma unroll
    for (int j=0;j<4;j++)
        *(float4*)&tile[row][c0+j*4] = *(const float4*)&src[row*64 + c0 + j*4];
    __syncthreads();
    #pragma unroll
    for (int j=0;j<16;j++){
        float v = tile[c0+j][row];
        __nv_bfloat16 hi = __float2bfloat16(v);
        __nv_bfloat16 lo = __float2bfloat16(v - __bfloat162float(hi));
        size_t di = (size_t)u*4096 + row*64 + c0 + j;
        g_mhd_h[di] = hi; g_mhd_l[di] = lo;
    }
}

// ---------------- K1a: loraA partial (split-K): acc over k-slice, no tanh ----------------
__global__ __launch_bounds__(256) void k_loraA_part(const float* __restrict__ x,
                                                    const float* __restrict__ mu_x,
                                                    const float* __restrict__ Aw){
    __shared__ float zsm[64][36];
    __shared__ float wsmT[32][34];
    int g  = blockIdx.y;
    int kz = blockIdx.z;
    int m0 = blockIdx.x*64;
    int tid = threadIdx.x;
    int n = tid & 31, ty = tid >> 5;
    ull acc2[8];
    #pragma unroll
    for (int i=0;i<8;i++) acc2[i]=0ull;
    const float* wbase = Aw + (size_t)g*Edim*Rdim;
    int kbeg = kz*(Edim/KSPLIT), kend = kbeg + Edim/KSPLIT;
    for (int k0=kbeg;k0<kend;k0+=32){
        #pragma unroll
        for (int j=0;j<2;j++){
            int f = tid + j*256;
            int row = f>>3, c4 = (f&7)*4;
            int m = m0 + row;
            float4 xv = *(const float4*)&x[(size_t)m*Edim + k0 + c4];
            float4 lx = make_float4(0.f,0.f,0.f,0.f);
            if (m & (Tdim-1)) lx = *(const float4*)&x[(size_t)(m-1)*Edim + k0 + c4];
            float4 mu = *(const float4*)&mu_x[k0 + c4];
            float4 z;
            { float d=lx.x-xv.x; z.x = xv.x + d*(xv.x + d*mu.x); }
            { float d=lx.y-xv.y; z.y = xv.y + d*(xv.y + d*mu.y); }
            { float d=lx.z-xv.z; z.z = xv.z + d*(xv.z + d*mu.z); }
            { float d=lx.w-xv.w; z.w = xv.w + d*(xv.w + d*mu.w); }
            *(float4*)&zsm[row][c4] = z;
        }
        {
            int kk = tid>>3, r4 = (tid&7)*4;
            float4 wv = *(const float4*)&wbase[(size_t)(k0+kk)*Rdim + r4];
            wsmT[r4+0][kk] = wv.x; wsmT[r4+1][kk] = wv.y;
            wsmT[r4+2][kk] = wv.z; wsmT[r4+3][kk] = wv.w;
        }
        __syncthreads();
        #pragma unroll
        for (int kk2=0;kk2<16;kk2++){
            ull b2 = *(const ull*)&wsmT[n][2*kk2];
            #pragma unroll
            for (int i=0;i<8;i++){
                ull a2 = *(const ull*)&zsm[ty*8+i][2*kk2];
                fma2(acc2[i], a2, b2);
            }
        }
        __syncthreads();
    }
    #pragma unroll
    for (int i=0;i<8;i++){
        float2 p = unpack2(acc2[i]);
        g_hdnp[(size_t)kz*Mdim*192 + (size_t)(m0+ty*8+i)*192 + g*32 + n] = p.x + p.y;
    }
}

// ---------------- K1b: loraA finish: sum partials + bias, tanh ----------------
__global__ __launch_bounds__(256) void k_loraA_fin(const float* __restrict__ Ab){
    size_t idx = (size_t)blockIdx.x*256 + threadIdx.x;
    int gn = (int)(idx % 192);
    float s = Ab[gn];
    #pragma unroll
    for (int kz=0;kz<KSPLIT;kz++)
        s += g_hdnp[(size_t)kz*Mdim*192 + idx];
    g_hdn[idx] = tanhf(s);
}

// ---------------- K2: dd = x + diff*(lam + hdn@Bw + Bb) -> bf16 hi/lo (R8 proven) ----------------
__global__ __launch_bounds__(256) void k_loraB(const float* __restrict__ x,
                                               const float* __restrict__ Bw,
                                               const float* __restrict__ lam,
                                               const float* __restrict__ Bb){
    __shared__ float hsm[16][32];
    int g  = blockIdx.z;
    int m0 = blockIdx.y*16;
    int tid = threadIdx.x;
    int e  = blockIdx.x*256 + tid;
    float wreg[32];
    const float* wb = Bw + (size_t)g*Rdim*Edim + e;
    #pragma unroll
    for (int r=0;r<32;r++) wreg[r] = wb[(size_t)r*Edim];
    {
        int f = tid;     hsm[f>>5][f&31] = g_hdn[(size_t)(m0+(f>>5))*192 + g*32 + (f&31)];
        f = tid + 256;   hsm[f>>5][f&31] = g_hdn[(size_t)(m0+(f>>5))*192 + g*32 + (f&31)];
    }
    __syncthreads();
    float base = lam[g*Edim + e] + Bb[g*Edim + e];
    #pragma unroll
    for (int mm=0;mm<16;mm++){
        float acc = base;
        #pragma unroll
        for (int r=0;r<32;r++) acc += hsm[mm][r]*wreg[r];
        int m = m0 + mm;
        size_t xi = (size_t)m*Edim + e;
        float xv = x[xi];
        float lx = (m & (Tdim-1)) ? x[xi - Edim] : 0.f;
        float ddv = xv + (lx - xv)*acc;
        __nv_bfloat16 hi = __float2bfloat16(ddv);
        __nv_bfloat16 lo = __float2bfloat16(ddv - __bfloat162float(hi));
        if (g == 5){ g_gah[xi] = hi; g_gal[xi] = lo; }
        else {
            size_t di = ((size_t)m*5 + g)*Edim + e;
            g_ddh[di] = hi; g_ddl[di] = lo;
        }
    }
}

// ---------------- K3: per-head 64x64 GEMM via HMMA bf16-split ----------------
#define PH_SMEM 49152
__global__ __launch_bounds__(256)
void k_headgemm(const float* __restrict__ unused){
    extern __shared__ char smg[];
    uint32_t dynb = smem_u32(smg);
    uint32_t db = (dynb + 1023u) & ~1023u;
    char* dptr = smg + (db - dynb);
    int tid = threadIdx.x, wid = tid>>5, lane = tid&31;
    int u = blockIdx.y;
    int g = u>>4, h = u&15;
    int mBase = blockIdx.x*128;
    int wm = (wid&3)*32, wn = (wid>>2)*32;
    uint32_t sAh = db, sAl = db + 16384, sBh = db + 32768, sBl = db + 40960;
    #pragma unroll
    for (int k=0;k<4;k++){
        int idx = tid + k*256;
        int row = idx>>3, c = idx&7;
        size_t si = ((size_t)(mBase+row)*5 + g)*Edim + h*64 + c*8;
        uint32_t swo = SW128((uint32_t)(row*128 + c*16));
        *(uint4*)(dptr + swo)          = *(const uint4*)&g_ddh[si];
        *(uint4*)(dptr + 16384 + swo)  = *(const uint4*)&g_ddl[si];
    }
    #pragma unroll
    for (int k=0;k<2;k++){
        int idx = tid + k*256;
        int row = idx>>3, c = idx&7;
        size_t si = (size_t)u*4096 + row*64 + c*8;
        uint32_t swo = SW128((uint32_t)(row*128 + c*16));
        *(uint4*)(dptr + 32768 + swo)  = *(const uint4*)&g_mhd_h[si];
        *(uint4*)(dptr + 40960 + swo)  = *(const uint4*)&g_mhd_l[si];
    }
    __syncthreads();
    float acc[2][4][4];
    #pragma unroll
    for (int mt=0;mt<2;mt++)
        #pragma unroll
        for (int nt=0;nt<4;nt++)
            #pragma unroll
            for (int j=0;j<4;j++) acc[mt][nt][j]=0.f;
    #pragma unroll
    for (int ks=0;ks<4;ks++){
        uint32_t ah[2][4], al[2][4];
        #pragma unroll
        for (int mt=0;mt<2;mt++){
            uint32_t off = SW128((uint32_t)((wm+mt*16+(lane&15))*128 + ks*32 + (lane>>4)*16));
            LDSM4(ah[mt], sAh + off);
            LDSM4(al[mt], sAl + off);
        }
        uint32_t bh[2][4], bl[2][4];
        #pragma unroll
        for (int p=0;p<2;p++){
            int brow = wn + p*16 + ((lane>>4)&1)*8 + (lane&7);
            uint32_t off = SW128((uint32_t)(brow*128 + ks*32 + ((lane>>3)&1)*16));
            LDSM4(bh[p], sBh + off);
            LDSM4(bl[p], sBl + off);
        }
        #pragma unroll
        for (int mt=0;mt<2;mt++){
            #pragma unroll
            for (int nt=0;nt<4;nt++){
                int p = nt>>1, o = (nt&1)*2;
                MMA_BF16(acc[mt][nt], ah[mt], bh[p][o], bh[p][o+1]);
                MMA_BF16(acc[mt][nt], ah[mt], bl[p][o], bl[p][o+1]);
                MMA_BF16(acc[mt][nt], al[mt], bh[p][o], bh[p][o+1]);
            }
        }
    }
    int gr = lane>>2, gc = (lane&3)*2;
    #pragma unroll
    for (int mt=0;mt<2;mt++){
        #pragma unroll
        for (int nt=0;nt<4;nt++){
            int row = mBase + wm + mt*16 + gr;
            int col = h*64 + wn + nt*8 + gc;
            size_t o0 = (size_t)row*5*Edim + (size_t)g*Edim + col;
            size_t o1 = (size_t)(row+8)*5*Edim + (size_t)g*Edim + col;
            *(float2*)&g_proj[o0] = make_float2(acc[mt][nt][0], acc[mt][nt][1]);
            *(float2*)&g_proj[o1] = make_float2(acc[mt][nt][2], acc[mt][nt][3]);
        }
    }
}

// ---------------- K3b: fused decay lora + parallel vr ----------------
__global__ __launch_bounds__(256) void k_wdecay(const float* __restrict__ wlam,
                                                const float* __restrict__ wA,
                                                const float* __restrict__ wB){
    __shared__ float asm_[64][68];
    __shared__ float wsm[64][68];
    int h = blockIdx.y;
    int m0 = blockIdx.x*64;
    int tid = threadIdx.x;
    {
        int row = tid>>2, q = tid&3;
        const float* v = g_proj + ((size_t)(m0+row)*5+1)*Edim + h*64 + q*16;
        const float* r = g_proj + ((size_t)(m0+row)*5+2)*Edim + h*64 + q*16;
        float s = 0.f;
        #pragma unroll
        for (int j=0;j<4;j++){
            float4 vv = *(const float4*)&v[j*4];
            float4 rr = *(const float4*)&r[j*4];
            s += vv.x*rr.x + vv.y*rr.y + vv.z*rr.z + vv.w*rr.w;
        }
        s += __shfl_xor_sync(0xffffffffu, s, 1);
        s += __shfl_xor_sync(0xffffffffu, s, 2);
        if (q==0) g_vr[(m0+row)*Hdim + h] = s;
    }
    #pragma unroll
    for (int j=0;j<4;j++){
        int f = tid + j*256;
        int row = f>>4, c4 = (f&15)*4;
        *(float4*)&asm_[row][c4] =
            *(const float4*)&g_proj[(size_t)(m0+row)*5*Edim + 3*Edim + h*64 + c4];
        *(float4*)&wsm[row][c4] = *(const float4*)&wA[(size_t)h*4096 + row*64 + c4];
    }
    __syncthreads();
    int tx = tid&15, ty = tid>>4;
    int n0 = tx*4, m0r = ty*4;
    ull acc[4][2];
    #pragma unroll
    for (int i=0;i<4;i++){ acc[i][0]=0ull; acc[i][1]=0ull; }
    #pragma unroll 16
    for (int k=0;k<64;k++){
        ull b01 = *(const ull*)&wsm[k][n0];
        ull b23 = *(const ull*)&wsm[k][n0+2];
        #pragma unroll
        for (int i=0;i<4;i++){
            float a = asm_[m0r+i][k];
            ull a2 = pack2(a, a);
            fma2(acc[i][0], a2, b01);
            fma2(acc[i][1], a2, b23);
        }
    }
    __syncthreads();
    #pragma unroll
    for (int i=0;i<4;i++){
        float2 lo = unpack2(acc[i][0]), hi = unpack2(acc[i][1]);
        *(float4*)&asm_[m0r+i][n0] =
            make_float4(tanhf(lo.x), tanhf(lo.y), tanhf(hi.x), tanhf(hi.y));
        acc[i][0]=0ull; acc[i][1]=0ull;
    }
    #pragma unroll
    for (int j=0;j<4;j++){
        int f = tid + j*256;
        int row = f>>4, c4 = (f&15)*4;
        *(float4*)&wsm[row][c4] = *(const float4*)&wB[(size_t)h*4096 + row*64 + c4];
    }
    __syncthreads();
    #pragma unroll 16
    for (int k=0;k<64;k++){
        ull b01 = *(const ull*)&wsm[k][n0];
        ull b23 = *(const ull*)&wsm[k][n0+2];
        #pragma unroll
        for (int i=0;i<4;i++){
            float a = asm_[m0r+i][k];
            ull a2 = pack2(a, a);
            fma2(acc[i][0], a2, b01);
            fma2(acc[i][1], a2, b23);
        }
    }
    #pragma unroll
    for (int i=0;i<4;i++){
        float2 lo = unpack2(acc[i][0]), hi = unpack2(acc[i][1]);
        float v[4] = {lo.x, lo.y, hi.x, hi.y};
        #pragma unroll
        for (int j=0;j<4;j++)
            v[j] = expf(-expf(v[j] + wlam[h*64 + n0 + j]));
        *(float4*)&g_wdec[(size_t)(m0+m0r+i)*Edim + h*64 + n0] =
            make_float4(v[0],v[1],v[2],v[3]);
    }
}

// ---------------- K4: HMMA bf16-split big GEMM ----------------
#define HS_BUF 16384
#define HS_SMEM (4*HS_BUF + 1024)
__global__ __launch_bounds__(256)
void k_gemm_hmma(const __nv_bfloat16* __restrict__ Ah, const __nv_bfloat16* __restrict__ Al,
                 const __nv_bfloat16* __restrict__ Bh, const __nv_bfloat16* __restrict__ Bl,
                 const float* __restrict__ bias, float* __restrict__ C){
    extern __shared__ char smg[];
    uint32_t dynb = smem_u32(smg);
    uint32_t db = (dynb + 1023u) & ~1023u;
    char* dptr = smg + (db - dynb);
    int tid = threadIdx.x, wid = tid>>5, lane = tid&31;
    int mBase = blockIdx.x*128, nBase = blockIdx.y*128;
    int wm = (wid&1)*64, wn = (wid>>1)*32;
    uint32_t sAh = db, sAl = db + HS_BUF, sBh = db + 2*HS_BUF, sBl = db + 3*HS_BUF;
    float acc[4][4][4];
    #pragma unroll
    for (int mt=0;mt<4;mt++)
        #pragma unroll
        for (int nt=0;nt<4;nt++)
            #pragma unroll
            for (int j=0;j<4;j++) acc[mt][nt][j]=0.f;
    int lrow = tid>>3, lc = tid&7;
    uint4 pa[4], pal[4], pb[4], pbl[4];
    #pragma unroll
    for (int jj=0;jj<4;jj++){
        int row = lrow + jj*32;
        pa[jj]  = *(const uint4*)&Ah[(size_t)(mBase+row)*Edim + lc*8];
        pal[jj] = *(const uint4*)&Al[(size_t)(mBase+row)*Edim + lc*8];
        pb[jj]  = *(const uint4*)&Bh[(size_t)(nBase+row)*Edim + lc*8];
        pbl[jj] = *(const uint4*)&Bl[(size_t)(nBase+row)*Edim + lc*8];
    }
    for (int i=0;i<16;i++){
        #pragma unroll
        for (int jj=0;jj<4;jj++){
            int row = lrow + jj*32;
            uint32_t swo = SW128((uint32_t)(row*128 + lc*16));
            *(uint4*)(dptr + swo)            = pa[jj];
            *(uint4*)(dptr + HS_BUF + swo)   = pal[jj];
            *(uint4*)(dptr + 2*HS_BUF + swo) = pb[jj];
            *(uint4*)(dptr + 3*HS_BUF + swo) = pbl[jj];
        }
        __syncthreads();
        if (i+1 < 16){
            int k0 = (i+1)*64;
            #pragma unroll
            for (int jj=0;jj<4;jj++){
                int row = lrow + jj*32;
                pa[jj]  = *(const uint4*)&Ah[(size_t)(mBase+row)*Edim + k0 + lc*8];
                pal[jj] = *(const uint4*)&Al[(size_t)(mBase+row)*Edim + k0 + lc*8];
                pb[jj]  = *(const uint4*)&Bh[(size_t)(nBase+row)*Edim + k0 + lc*8];
                pbl[jj] = *(const uint4*)&Bl[(size_t)(nBase+row)*Edim + k0 + lc*8];
            }
        }
        #pragma unroll
        for (int ks=0;ks<4;ks++){
            uint32_t ah[4][4], al[4][4];
            #pragma unroll
            for (int mt=0;mt<4;mt++){
                uint32_t off = SW128((uint32_t)((wm+mt*16+(lane&15))*128 + ks*32 + (lane>>4)*16));
                LDSM4(ah[mt], sAh + off);
                LDSM4(al[mt], sAl + off);
            }
            uint32_t bh[2][4], bl[2][4];
            #pragma unroll
            for (int p=0;p<2;p++){
                int brow = wn + p*16 + ((lane>>4)&1)*8 + (lane&7);
                uint32_t off = SW128((uint32_t)(brow*128 + ks*32 + ((lane>>3)&1)*16));
                LDSM4(bh[p], sBh + off);
                LDSM4(bl[p], sBl + off);
            }
            #pragma unroll
            for (int mt=0;mt<4;mt++){
                #pragma unroll
                for (int nt=0;nt<4;nt++){
                    int p = nt>>1, o = (nt&1)*2;
                    MMA_BF16(acc[mt][nt], ah[mt], bh[p][o], bh[p][o+1]);
                    MMA_BF16(acc[mt][nt], ah[mt], bl[p][o], bl[p][o+1]);
                    MMA_BF16(acc[mt][nt], al[mt], bh[p][o], bh[p][o+1]);
                }
            }
        }
        __syncthreads();
    }
    int gr = lane>>2, gc = (lane&3)*2;
    #pragma unroll
    for (int mt=0;mt<4;mt++){
        #pragma unroll
        for (int nt=0;nt<4;nt++){
            int row = mBase + wm + mt*16 + gr;
            int col = nBase + wn + nt*8 + gc;
            float b0 = bias ? bias[col] : 0.f;
            float b1 = bias ? bias[col+1] : 0.f;
            *(float2*)&C[(size_t)row*Edim + col] =
                make_float2(acc[mt][nt][0] + b0, acc[mt][nt][1] + b1);
            *(float2*)&C[(size_t)(row+8)*Edim + col] =
                make_float2(acc[mt][nt][2] + b0, acc[mt][nt][3] + b1);
        }
    }
}

// ---------------- K6a: chunk-local recurrence ----------------
__global__ __launch_bounds__(256) void k_recur1(){
    int unit = blockIdx.x;
    int c = unit & (NC-1);
    int bh = unit >> 4;
    int b = bh >> 4, h = bh & 15;
    int tid = threadIdx.x;
    int row = tid >> 2, q = tid & 3, c0 = q*16;
    __shared__ float sk[CH][64], su[CH][64], sw[CH][64], sv[CH][64], sr[CH][64];
    __shared__ float svr[CH], sout[CH][64], swcum[CH][64];
    ull S2[8];
    #pragma unroll
    for (int j=0;j<8;j++) S2[j] = 0ull;
    float wcumr = 1.f;
    int mbase = b*Tdim + c*CHK;
    float rk[4], ru[4], rw[4], rv[4], rr[4], rvr = 0.f;
    #pragma unroll
    for (int it=0;it<4;it++){
        int idx = tid + it*256; int st = idx>>6, col = idx&63;
        size_t m = (size_t)(mbase + st);
        const float* bp = g_proj + m*5*Edim + h*64 + col;
        rk[it] = bp[0]; rv[it] = bp[Edim]; rr[it] = bp[2*Edim]; ru[it] = bp[4*Edim];
        rw[it] = g_wdec[m*Edim + h*64 + col];
    }
    if (tid < CH) rvr = g_vr[(mbase+tid)*Hdim + h];
    for (int cc=0; cc<CHK/CH; cc++){
        #pragma unroll
        for (int it=0;it<4;it++){
            int idx = tid + it*256; int st = idx>>6, col = idx&63;
            sk[st][col]=rk[it]; su[st][col]=ru[it]; sw[st][col]=rw[it];
            sv[st][col]=rv[it]; sr[st][col]=rr[it];
        }
        if (tid < CH) svr[tid] = rvr;
        __syncthreads();
        if (cc+1 < CHK/CH){
            int t0 = (cc+1)*CH;
            #pragma unroll
            for (int it=0;it<4;it++){
                int idx = tid + it*256; int st = idx>>6, col = idx&63;
                size_t m = (size_t)(mbase + t0 + st);
                const float* bp = g_proj + m*5*Edim + h*64 + col;
                rk[it] = bp[0]; rv[it] = bp[Edim]; rr[it] = bp[2*Edim]; ru[it] = bp[4*Edim];
                rw[it] = g_wdec[m*Edim + h*64 + col];
            }
            if (tid < CH) rvr = g_vr[(mbase+t0+tid)*Hdim + h];
        }
        #pragma unroll
        for (int t=0;t<CH;t++){
            float kc = sk[t][row], wc = sw[t][row], uc = su[t][row], vc = svr[t];
            ull kc2 = pack2(kc, kc), wc2 = pack2(wc, wc);
            const ull* r2 = (const ull*)&sr[t][c0];
            const ull* v2 = (const ull*)&sv[t][c0];
            ull da0=0ull, da1=0ull, da2=0ull, da3=0ull;
            fma2(da0, S2[0], r2[0]); fma2(da1, S2[1], r2[1]);
            fma2(da2, S2[2], r2[2]); fma2(da3, S2[3], r2[3]);
            fma2(da0, S2[4], r2[4]); fma2(da1, S2[5], r2[5]);
            fma2(da2, S2[6], r2[6]); fma2(da3, S2[7], r2[7]);
            float2 p0 = unpack2(da0), p1 = unpack2(da1);
            float2 p2 = unpack2(da2), p3 = unpack2(da3);
            float dot = ((p0.x+p0.y)+(p1.x+p1.y)) + ((p2.x+p2.y)+(p3.x+p3.y));
            dot += __shfl_xor_sync(0xffffffffu, dot, 1);
            dot += __shfl_xor_sync(0xffffffffu, dot, 2);
            if (q==0){
                sout[t][row]  = uc*kc*vc + dot;
                swcum[t][row] = wcumr;
            }
            wcumr *= wc;
            #pragma unroll
            for (int j=0;j<8;j++){
                mul2(S2[j], wc2, S2[j]);
                fma2(S2[j], kc2, v2[j]);
            }
        }
        __syncthreads();
        #pragma unroll
        for (int it=0;it<4;it++){
            int idx = tid + it*256; int st = idx>>6, col = idx&63;
            size_t di = (size_t)(mbase + cc*CH + st)*Edim + h*64 + col;
            g_rwkv[di] = sout[st][col];
            g_wcum[di] = swcum[st][col];
        }
    }
    size_t sb = ((size_t)bh*NC + c)*4096 + row*64 + c0;
    #pragma unroll
    for (int j=0;j<8;j++)
        *(ull*)&g_send[sb + 2*j] = S2[j];
    if (q==0) g_wprod[((size_t)bh*NC + c)*64 + row] = wcumr;
}

// ---------------- K6b: sequential chunk combine ----------------
__global__ __launch_bounds__(256) void k_recur2(){
    int bh = blockIdx.x;
    int tid = threadIdx.x;
    int off = tid*16;
    int d = off >> 6;
    float4 S[4];
    #pragma unroll
    for (int j=0;j<4;j++) S[j] = make_float4(0.f,0.f,0.f,0.f);
    for (int c=0;c<NC;c++){
        size_t sb = ((size_t)bh*NC + c)*4096 + off;
        #pragma unroll
        for (int j=0;j<4;j++)
            *(float4*)&g_sstart[sb + j*4] = S[j];
        float wp = g_wprod[((size_t)bh*NC + c)*64 + d];
        #pragma unroll
        for (int j=0;j<4;j++){
            float4 se = *(const float4*)&g_send[sb + j*4];
            S[j].x = se.x + wp*S[j].x;
            S[j].y = se.y + wp*S[j].y;
            S[j].z = se.z + wp*S[j].z;
            S[j].w = se.w + wp*S[j].w;
        }
    }
}

// ---------------- K6c: cross-chunk correction ----------------
__global__ __launch_bounds__(256) void k_recur3(){
    __shared__ float rsm[64][68];
    __shared__ float ssm[64][68];
    int h = blockIdx.y;
    int m0 = blockIdx.x*64;
    int b = m0 >> 10;
    int c = (m0 & (Tdim-1)) >> 6;
    int bh = b*Hdim + h;
    const float* Sst = g_sstart + ((size_t)bh*NC + c)*4096;
    int tid = threadIdx.x;
    #pragma unroll
    for (int j=0;j<4;j++){
        int f = tid + j*256;
        int row = f>>4, c4 = (f&15)*4;
        *(float4*)&rsm[row][c4] =
            *(const float4*)&g_proj[(size_t)(m0+row)*5*Edim + 2*Edim + h*64 + c4];
        float4 sv = *(const float4*)&Sst[row*64 + c4];
        ssm[c4+0][row] = sv.x; ssm[c4+1][row] = sv.y;
        ssm[c4+2][row] = sv.z; ssm[c4+3][row] = sv.w;
    }
    __syncthreads();
    int tx = tid&15, ty = tid>>4;
    int n0 = tx*4, m0r = ty*4;
    ull acc[4][2];
    #pragma unroll
    for (int i=0;i<4;i++){ acc[i][0]=0ull; acc[i][1]=0ull; }
    #pragma unroll 16
    for (int k=0;k<64;k++){
        ull b01 = *(const ull*)&ssm[k][n0];
        ull b23 = *(const ull*)&ssm[k][n0+2];
        #pragma unroll
        for (int i=0;i<4;i++){
            float a = rsm[m0r+i][k];
            ull a2 = pack2(a, a);
            fma2(acc[i][0], a2, b01);
            fma2(acc[i][1], a2, b23);
        }
    }
    #pragma unroll
    for (int i=0;i<4;i++){
        float2 lo = unpack2(acc[i][0]), hi = unpack2(acc[i][1]);
        size_t di = (size_t)(m0+m0r+i)*Edim + h*64 + n0;
        float4 wc = *(const float4*)&g_wcum[di];
        float4 ov = *(const float4*)&g_rwkv[di];
        ov.x += wc.x*lo.x; ov.y += wc.y*lo.y;
        ov.z += wc.z*hi.x; ov.w += wc.w*hi.y;
        *(float4*)&g_rwkv[di] = ov;
    }
}

// ---------------- K7: GroupNorm * silu(gate) -> bf16 hi/lo ----------------
__global__ __launch_bounds__(256) void k_gn(const float* __restrict__ gamma,
                                            const float* __restrict__ beta){
    int unit = blockIdx.x*8 + (threadIdx.x>>5);
    int lane = threadIdx.x & 31;
    int m = unit>>4, h = unit&15;
    size_t base = (size_t)m*Edim + h*64;
    float v1 = g_rwkv[base + lane];
    float v2 = g_rwkv[base + 32 + lane];
    float s = v1+v2, sq = v1*v1 + v2*v2;
    #pragma unroll
    for (int o=16;o;o>>=1){
        s  += __shfl_xor_sync(0xffffffffu, s, o);
        sq += __shfl_xor_sync(0xffffffffu, sq, o);
    }
    float mean = s*(1.f/64.f);
    float var  = sq*(1.f/64.f) - mean*mean;
    float rstd = rsqrtf(var + 1e-3f);
    #pragma unroll
    for (int half=0; half<2; half++){
        int e = h*64 + half*32 + lane;
        float v = half ? v2 : v1;
        float nv = (v-mean)*rstd*gamma[e] + beta[e];
        float gg = g_gate[(size_t)m*Edim + e];
        float a = nv * (gg/(1.f+expf(-gg)));
        size_t di = (size_t)m*Edim + e;
        __nv_bfloat16 hi = __float2bfloat16(a);
        g_oah[di] = hi;
        g_oal[di] = __float2bfloat16(a - __bfloat162float(hi));
    }
}

extern "C" void kernel_launch(void* const* d_in, const int* in_sizes, int n_in,
                              void* d_out, int out_size) {
    const float* x    = (const float*)d_in[0];
    const float* mu_x = (const float*)d_in[1];
    const float* lam  = (const float*)d_in[2];
    const float* Aw   = (const float*)d_in[3];
    const float* Ab   = (const float*)d_in[4];
    const float* Bw   = (const float*)d_in[5];
    const float* Bb   = (const float*)d_in[6];
    const float* mhd  = (const float*)d_in[7];
    const float* gw   = (const float*)d_in[8];
    const float* wlam = (const float*)d_in[9];
    const float* wA   = (const float*)d_in[10];
    const float* wB   = (const float*)d_in[11];
    const float* gng  = (const float*)d_in[12];
    const float* gnb  = (const float*)d_in[13];
    const float* ow   = (const float*)d_in[14];
    const float* ob   = (const float*)d_in[15];
    float* out = (float*)d_out;

    float *p_gate;
    cudaGetSymbolAddress((void**)&p_gate, g_gate);
    __nv_bfloat16 *p_gah, *p_gal, *p_oah, *p_oal, *p_gwh, *p_gwl, *p_owh, *p_owl;
    cudaGetSymbolAddress((void**)&p_gah, g_gah);
    cudaGetSymbolAddress((void**)&p_gal, g_gal);
    cudaGetSymbolAddress((void**)&p_oah, g_oah);
    cudaGetSymbolAddress((void**)&p_oal, g_oal);
    cudaGetSymbolAddress((void**)&p_gwh, g_gwt_h);
    cudaGetSymbolAddress((void**)&p_gwl, g_gwt_l);
    cudaGetSymbolAddress((void**)&p_owh, g_owt_h);
    cudaGetSymbolAddress((void**)&p_owl, g_owt_l);

    static cudaStream_t s2 = nullptr;
    static cudaEvent_t e_lb = nullptr, e_gate = nullptr;
    static bool attr_done = false;
    if (!attr_done){
        cudaFuncSetAttribute(k_gemm_hmma, cudaFuncAttributeMaxDynamicSharedMemorySize, HS_SMEM);
        cudaFuncSetAttribute(k_headgemm,  cudaFuncAttributeMaxDynamicSharedMemorySize, PH_SMEM + 1024);
        cudaStreamCreateWithFlags(&s2, cudaStreamNonBlocking);
        cudaEventCreateWithFlags(&e_lb,   cudaEventDisableTiming);
        cudaEventCreateWithFlags(&e_gate, cudaEventDisableTiming);
        attr_done = true;
    }

    k_wprep<<<dim3(Edim/32, Edim/32, 2), 256>>>(gw, ow);
    k_mhdprep<<<80, 256>>>(mhd);
    k_loraA_part<<<dim3(Mdim/64, 6, KSPLIT), 256>>>(x, mu_x, Aw);
    k_loraA_fin<<<(Mdim*192)/256, 256>>>(Ab);
    k_loraB<<<dim3(Edim/256, Mdim/16, 6), 256>>>(x, Bw, lam, Bb);
    cudaEventRecord(e_lb, 0);

    cudaStreamWaitEvent(s2, e_lb, 0);
    k_gemm_hmma<<<dim3(Mdim/128, Edim/128), 256, HS_SMEM, s2>>>(p_gah, p_gal, p_gwh, p_gwl, nullptr, p_gate);
    cudaEventRecord(e_gate, s2);

    k_headgemm<<<dim3(Mdim/128, 80), 256, PH_SMEM + 1024>>>(nullptr);
    k_wdecay<<<dim3(Mdim/64, 16), 256>>>(wlam, wA, wB);
    k_recur1<<<Bdim*Hdim*NC, 256>>>();
    k_recur2<<<Bdim*Hdim, 256>>>();
    k_recur3<<<dim3(Mdim/64, Hdim), 256>>>();
    cudaStreamWaitEvent(0, e_gate, 0);
    k_gn<<<(Mdim*Hdim)/8, 256>>>(gng, gnb);
    k_gemm_hmma<<<dim3(Mdim/128, Edim/128), 256, HS_SMEM>>>(p_oah, p_oal, p_owh, p_owl, ob, out);
}

// round 16
// speedup vs baseline: 1.1655x; 1.0089x over previous
#include <cuda_runtime.h>
#include <cuda_bf16.h>
#include <cstdint>

#define Bdim 2
#define Tdim 1024
#define Edim 1024
#define Hdim 16
#define Ddim 64
#define Rdim 32
#define Mdim (Bdim*Tdim)
#define CH 16
#define NC 16
#define CHK (Tdim/NC)
#define KSPLIT 4

typedef unsigned long long ull;

// ---------------- scratch ----------------
__device__ float g_hdnp[(size_t)KSPLIT*Mdim*6*Rdim];
__device__ float g_proj[(size_t)Mdim*5*Edim];
__device__ float g_gate[(size_t)Mdim*Edim];
__device__ float g_wdec[(size_t)Mdim*Edim];
__device__ float g_vr  [(size_t)Mdim*Hdim];
__device__ float g_rwkv[(size_t)Mdim*Edim];
__device__ float g_wcum[(size_t)Mdim*Edim];
__device__ float g_send[(size_t)Bdim*Hdim*NC*4096];
__device__ float g_sstart[(size_t)Bdim*Hdim*NC*4096];
__device__ float g_wprod[(size_t)Bdim*Hdim*NC*64];
__device__ float g_lbb [(size_t)6*Edim];
__device__ __align__(16) __nv_bfloat16 g_hdnh[(size_t)Mdim*6*Rdim];
__device__ __align__(16) __nv_bfloat16 g_hdnl[(size_t)Mdim*6*Rdim];
__device__ __align__(16) __nv_bfloat16 g_bwth[(size_t)6*Edim*Rdim];
__device__ __align__(16) __nv_bfloat16 g_bwtl[(size_t)6*Edim*Rdim];
__device__ __align__(16) __nv_bfloat16 g_ddh[(size_t)Mdim*5*Edim];
__device__ __align__(16) __nv_bfloat16 g_ddl[(size_t)Mdim*5*Edim];
__device__ __align__(16) __nv_bfloat16 g_gah[(size_t)Mdim*Edim];
__device__ __align__(16) __nv_bfloat16 g_gal[(size_t)Mdim*Edim];
__device__ __align__(16) __nv_bfloat16 g_oah[(size_t)Mdim*Edim];
__device__ __align__(16) __nv_bfloat16 g_oal[(size_t)Mdim*Edim];
__device__ __align__(16) __nv_bfloat16 g_gwt_h[(size_t)Edim*Edim];
__device__ __align__(16) __nv_bfloat16 g_gwt_l[(size_t)Edim*Edim];
__device__ __align__(16) __nv_bfloat16 g_owt_h[(size_t)Edim*Edim];
__device__ __align__(16) __nv_bfloat16 g_owt_l[(size_t)Edim*Edim];
__device__ __align__(16) __nv_bfloat16 g_mhd_h[(size_t)80*4096];
__device__ __align__(16) __nv_bfloat16 g_mhd_l[(size_t)80*4096];

// ---------------- helpers ----------------
__device__ __forceinline__ ull pack2(float lo, float hi){
    ull r; asm("mov.b64 %0, {%1, %2};" : "=l"(r) : "f"(lo), "f"(hi)); return r;
}
__device__ __forceinline__ void fma2(ull& d, ull a, ull b){
    asm("fma.rn.f32x2 %0, %1, %2, %3;" : "=l"(d) : "l"(a), "l"(b), "l"(d));
}
__device__ __forceinline__ void mul2(ull& d, ull a, ull b){
    asm("mul.rn.f32x2 %0, %1, %2;" : "=l"(d) : "l"(a), "l"(b));
}
__device__ __forceinline__ float2 unpack2(ull v){
    float lo, hi; asm("mov.b64 {%0, %1}, %2;" : "=f"(lo), "=f"(hi) : "l"(v));
    return make_float2(lo, hi);
}
__device__ __forceinline__ uint32_t smem_u32(const void* p){
    uint32_t a; asm("{ .reg .u64 t; cvta.to.shared.u64 t, %1; cvt.u32.u64 %0, t; }" : "=r"(a) : "l"(p));
    return a;
}
#define SW128(o) ((o) ^ ((((uint32_t)(o))>>3) & 0x70u))

#define LDSM4(r, addr) \
    asm volatile("ldmatrix.sync.aligned.m8n8.x4.shared.b16 {%0,%1,%2,%3}, [%4];" \
        : "=r"((r)[0]), "=r"((r)[1]), "=r"((r)[2]), "=r"((r)[3]) : "r"(addr))

#define MMA_BF16(c, a, b0, b1) \
    asm volatile("mma.sync.aligned.m16n8k16.row.col.f32.bf16.bf16.f32 " \
        "{%0,%1,%2,%3}, {%4,%5,%6,%7}, {%8,%9}, {%0,%1,%2,%3};" \
        : "+f"((c)[0]), "+f"((c)[1]), "+f"((c)[2]), "+f"((c)[3]) \
        : "r"((a)[0]), "r"((a)[1]), "r"((a)[2]), "r"((a)[3]), "r"(b0), "r"(b1))

// ---------------- K0: transpose + bf16-split E x E weights ----------------
__global__ __launch_bounds__(256) void k_wprep(const float* __restrict__ gw,
                                               const float* __restrict__ ow){
    __shared__ float tile[32][33];
    const float* src = blockIdx.z ? ow : gw;
    __nv_bfloat16* dh = blockIdx.z ? g_owt_h : g_gwt_h;
    __nv_bfloat16* dl = blockIdx.z ? g_owt_l : g_gwt_l;
    int k0 = blockIdx.x*32, n0 = blockIdx.y*32;
    int tid = threadIdx.x;
    int r = tid>>3, c = (tid&7)*4;
    float4 v4 = *(const float4*)&src[(size_t)(k0+r)*Edim + n0 + c];
    tile[r][c+0] = v4.x; tile[r][c+1] = v4.y;
    tile[r][c+2] = v4.z; tile[r][c+3] = v4.w;
    __syncthreads();
    #pragma unroll
    for (int j=0;j<4;j++){
        float v = tile[c+j][r];
        __nv_bfloat16 hi = __float2bfloat16(v);
        __nv_bfloat16 lo = __float2bfloat16(v - __bfloat162float(hi));
        size_t di = (size_t)(n0+r)*Edim + k0 + c + j;
        dh[di] = hi; dl[di] = lo;
    }
}

// ---------------- K0b: transpose + split per-head weights ----------------
__global__ __launch_bounds__(256) void k_mhdprep(const float* __restrict__ mhd){
    __shared__ float tile[64][68];
    int u = blockIdx.x;
    int tid = threadIdx.x;
    int row = tid>>2, c0 = (tid&3)*16;
    const float* src = mhd + (size_t)u*4096;
    #pragma unroll
    for (int j=0;j<4;j++)
        *(float4*)&tile[row][c0+j*4] = *(const float4*)&src[row*64 + c0 + j*4];
    __syncthreads();
    #pragma unroll
    for (int j=0;j<16;j++){
        float v = tile[c0+j][row];
        __nv_bfloat16 hi = __float2bfloat16(v);
        __nv_bfloat16 lo = __float2bfloat16(v - __bfloat162float(hi));
        size_t di = (size_t)u*4096 + row*64 + c0 + j;
        g_mhd_h[di] = hi; g_mhd_l[di] = lo;
    }
}

// ---------------- K0c: Bw[g][r][e] -> bwt[g][e][r] bf16 hi/lo; lbb = lam+Bb ----------------
__global__ __launch_bounds__(256) void k_bwprep(const float* __restrict__ Bw,
                                                const float* __restrict__ lam,
                                                const float* __restrict__ Bb){
    int g = blockIdx.y;
    int e = blockIdx.x*256 + threadIdx.x;
    __nv_bfloat16 hib[32], lob[32];
    #pragma unroll
    for (int r=0;r<32;r++){
        float v = Bw[((size_t)g*Rdim + r)*Edim + e];
        __nv_bfloat16 hi = __float2bfloat16(v);
        hib[r] = hi;
        lob[r] = __float2bfloat16(v - __bfloat162float(hi));
    }
    size_t db = ((size_t)g*Edim + e)*Rdim;
    #pragma unroll
    for (int j=0;j<4;j++){
        *(uint4*)&g_bwth[db + j*8] = *(uint4*)&hib[j*8];
        *(uint4*)&g_bwtl[db + j*8] = *(uint4*)&lob[j*8];
    }
    g_lbb[g*Edim + e] = lam[g*Edim + e] + Bb[g*Edim + e];
}

// ---------------- K1a: loraA partial (split-K) ----------------
__global__ __launch_bounds__(256) void k_loraA_part(const float* __restrict__ x,
                                                    const float* __restrict__ mu_x,
                                                    const float* __restrict__ Aw){
    __shared__ float zsm[64][36];
    __shared__ float wsmT[32][34];
    int g  = blockIdx.y;
    int kz = blockIdx.z;
    int m0 = blockIdx.x*64;
    int tid = threadIdx.x;
    int n = tid & 31, ty = tid >> 5;
    ull acc2[8];
    #pragma unroll
    for (int i=0;i<8;i++) acc2[i]=0ull;
    const float* wbase = Aw + (size_t)g*Edim*Rdim;
    int kbeg = kz*(Edim/KSPLIT), kend = kbeg + Edim/KSPLIT;
    for (int k0=kbeg;k0<kend;k0+=32){
        #pragma unroll
        for (int j=0;j<2;j++){
            int f = tid + j*256;
            int row = f>>3, c4 = (f&7)*4;
            int m = m0 + row;
            float4 xv = *(const float4*)&x[(size_t)m*Edim + k0 + c4];
            float4 lx = make_float4(0.f,0.f,0.f,0.f);
            if (m & (Tdim-1)) lx = *(const float4*)&x[(size_t)(m-1)*Edim + k0 + c4];
            float4 mu = *(const float4*)&mu_x[k0 + c4];
            float4 z;
            { float d=lx.x-xv.x; z.x = xv.x + d*(xv.x + d*mu.x); }
            { float d=lx.y-xv.y; z.y = xv.y + d*(xv.y + d*mu.y); }
            { float d=lx.z-xv.z; z.z = xv.z + d*(xv.z + d*mu.z); }
            { float d=lx.w-xv.w; z.w = xv.w + d*(xv.w + d*mu.w); }
            *(float4*)&zsm[row][c4] = z;
        }
        {
            int kk = tid>>3, r4 = (tid&7)*4;
            float4 wv = *(const float4*)&wbase[(size_t)(k0+kk)*Rdim + r4];
            wsmT[r4+0][kk] = wv.x; wsmT[r4+1][kk] = wv.y;
            wsmT[r4+2][kk] = wv.z; wsmT[r4+3][kk] = wv.w;
        }
        __syncthreads();
        #pragma unroll
        for (int kk2=0;kk2<16;kk2++){
            ull b2 = *(const ull*)&wsmT[n][2*kk2];
            #pragma unroll
            for (int i=0;i<8;i++){
                ull a2 = *(const ull*)&zsm[ty*8+i][2*kk2];
                fma2(acc2[i], a2, b2);
            }
        }
        __syncthreads();
    }
    #pragma unroll
    for (int i=0;i<8;i++){
        float2 p = unpack2(acc2[i]);
        g_hdnp[(size_t)kz*Mdim*192 + (size_t)(m0+ty*8+i)*192 + g*32 + n] = p.x + p.y;
    }
}

// ---------------- K1b: loraA finish -> bf16 hi/lo ----------------
__global__ __launch_bounds__(256) void k_loraA_fin(const float* __restrict__ Ab){
    size_t idx = (size_t)blockIdx.x*256 + threadIdx.x;
    int gn = (int)(idx % 192);
    float s = Ab[gn];
    #pragma unroll
    for (int kz=0;kz<KSPLIT;kz++)
        s += g_hdnp[(size_t)kz*Mdim*192 + idx];
    float v = tanhf(s);
    __nv_bfloat16 hi = __float2bfloat16(v);
    g_hdnh[idx] = hi;
    g_hdnl[idx] = __float2bfloat16(v - __bfloat162float(hi));
}

// ---------------- K2: loraB via HMMA + smem-staged ddlerp epilogue ----------------
#define LB_BUF 16384
#define LB_SMEM (128*132*4 + 1024)
__global__ __launch_bounds__(256)
void k_loraB_hmma(const float* __restrict__ x){
    extern __shared__ char smg[];
    uint32_t dynb = smem_u32(smg);
    uint32_t db = (dynb + 1023u) & ~1023u;
    char* dptr = smg + (db - dynb);
    float* accsm = (float*)dptr;
    int tid = threadIdx.x, wid = tid>>5, lane = tid&31;
    int g = blockIdx.z;
    int mBase = blockIdx.x*128, eBase = blockIdx.y*128;
    int wm = (wid&1)*64, wn = (wid>>1)*32;
    uint32_t sAh = db, sAl = db + LB_BUF, sBh = db + 2*LB_BUF, sBl = db + 3*LB_BUF;

    #pragma unroll
    for (int k=0;k<2;k++){
        int idx = tid + k*256;
        int row = idx>>2, c = idx&3;
        uint32_t swo = SW128((uint32_t)(row*128 + c*16));
        size_t ai = ((size_t)(mBase+row)*6 + g)*Rdim + c*8;
        *(uint4*)(dptr + swo)            = *(const uint4*)&g_hdnh[ai];
        *(uint4*)(dptr + LB_BUF + swo)   = *(const uint4*)&g_hdnl[ai];
        size_t bi = ((size_t)g*Edim + eBase+row)*Rdim + c*8;
        *(uint4*)(dptr + 2*LB_BUF + swo) = *(const uint4*)&g_bwth[bi];
        *(uint4*)(dptr + 3*LB_BUF + swo) = *(const uint4*)&g_bwtl[bi];
    }
    __syncthreads();

    float acc[4][4][4];
    #pragma unroll
    for (int mt=0;mt<4;mt++)
        #pragma unroll
        for (int nt=0;nt<4;nt++)
            #pragma unroll
            for (int j=0;j<4;j++) acc[mt][nt][j]=0.f;

    #pragma unroll
    for (int ks=0;ks<2;ks++){
        uint32_t ah[4][4], al[4][4];
        #pragma unroll
        for (int mt=0;mt<4;mt++){
            uint32_t off = SW128((uint32_t)((wm+mt*16+(lane&15))*128 + ks*32 + (lane>>4)*16));
            LDSM4(ah[mt], sAh + off);
            LDSM4(al[mt], sAl + off);
        }
        uint32_t bh[2][4], bl[2][4];
        #pragma unroll
        for (int p=0;p<2;p++){
            int brow = wn + p*16 + ((lane>>4)&1)*8 + (lane&7);
            uint32_t off = SW128((uint32_t)(brow*128 + ks*32 + ((lane>>3)&1)*16));
            LDSM4(bh[p], sBh + off);
            LDSM4(bl[p], sBl + off);
        }
        #pragma unroll
        for (int mt=0;mt<4;mt++){
            #pragma unroll
            for (int nt=0;nt<4;nt++){
                int p = nt>>1, o = (nt&1)*2;
                MMA_BF16(acc[mt][nt], ah[mt], bh[p][o], bh[p][o+1]);
                MMA_BF16(acc[mt][nt], ah[mt], bl[p][o], bl[p][o+1]);
                MMA_BF16(acc[mt][nt], al[mt], bh[p][o], bh[p][o+1]);
            }
        }
    }
    __syncthreads();
    int gr = lane>>2, gc = (lane&3)*2;
    #pragma unroll
    for (int mt=0;mt<4;mt++){
        #pragma unroll
        for (int nt=0;nt<4;nt++){
            int col = wn + nt*8 + gc;
            int r0 = wm + mt*16 + gr;
            *(float2*)&accsm[r0*132 + col]     = make_float2(acc[mt][nt][0], acc[mt][nt][1]);
            *(float2*)&accsm[(r0+8)*132 + col] = make_float2(acc[mt][nt][2], acc[mt][nt][3]);
        }
    }
    __syncthreads();
    #pragma unroll
    for (int j=0;j<16;j++){
        int lin = j*1024 + tid*4;
        int row = lin>>7, col = lin&127;
        float4 a = *(const float4*)&accsm[row*132 + col];
        int gm = mBase + row;
        int ge = eBase + col;
        float4 b = *(const float4*)&g_lbb[g*Edim + ge];
        size_t xi = (size_t)gm*Edim + ge;
        float4 xv = *(const float4*)&x[xi];
        float4 lx = make_float4(0.f,0.f,0.f,0.f);
        if (gm & (Tdim-1)) lx = *(const float4*)&x[xi - Edim];
        float d0 = xv.x + (lx.x - xv.x)*(a.x + b.x);
        float d1 = xv.y + (lx.y - xv.y)*(a.y + b.y);
        float d2 = xv.z + (lx.z - xv.z)*(a.z + b.z);
        float d3 = xv.w + (lx.w - xv.w)*(a.w + b.w);
        __nv_bfloat16 h0=__float2bfloat16(d0), h1=__float2bfloat16(d1);
        __nv_bfloat16 h2=__float2bfloat16(d2), h3=__float2bfloat16(d3);
        __align__(8) __nv_bfloat16 hb[4] = {h0,h1,h2,h3};
        __align__(8) __nv_bfloat16 lb[4] = {
            __float2bfloat16(d0-__bfloat162float(h0)),
            __float2bfloat16(d1-__bfloat162float(h1)),
            __float2bfloat16(d2-__bfloat162float(h2)),
            __float2bfloat16(d3-__bfloat162float(h3))};
        if (g == 5){
            *(uint2*)&g_gah[xi] = *(uint2*)hb;
            *(uint2*)&g_gal[xi] = *(uint2*)lb;
        } else {
            size_t di = ((size_t)gm*5 + g)*Edim + ge;
            *(uint2*)&g_ddh[di] = *(uint2*)hb;
            *(uint2*)&g_ddl[di] = *(uint2*)lb;
        }
    }
}

// ---------------- K3: per-head 64x64 GEMM via HMMA bf16-split ----------------
#define PH_SMEM 49152
__global__ __launch_bounds__(256)
void k_headgemm(const float* __restrict__ unused){
    extern __shared__ char smg[];
    uint32_t dynb = smem_u32(smg);
    uint32_t db = (dynb + 1023u) & ~1023u;
    char* dptr = smg + (db - dynb);
    int tid = threadIdx.x, wid = tid>>5, lane = tid&31;
    int u = blockIdx.y;
    int g = u>>4, h = u&15;
    int mBase = blockIdx.x*128;
    int wm = (wid&3)*32, wn = (wid>>2)*32;
    uint32_t sAh = db, sAl = db + 16384, sBh = db + 32768, sBl = db + 40960;
    #pragma unroll
    for (int k=0;k<4;k++){
        int idx = tid + k*256;
        int row = idx>>3, c = idx&7;
        size_t si = ((size_t)(mBase+row)*5 + g)*Edim + h*64 + c*8;
        uint32_t swo = SW128((uint32_t)(row*128 + c*16));
        *(uint4*)(dptr + swo)          = *(const uint4*)&g_ddh[si];
        *(uint4*)(dptr + 16384 + swo)  = *(const uint4*)&g_ddl[si];
    }
    #pragma unroll
    for (int k=0;k<2;k++){
        int idx = tid + k*256;
        int row = idx>>3, c = idx&7;
        size_t si = (size_t)u*4096 + row*64 + c*8;
        uint32_t swo = SW128((uint32_t)(row*128 + c*16));
        *(uint4*)(dptr + 32768 + swo)  = *(const uint4*)&g_mhd_h[si];
        *(uint4*)(dptr + 40960 + swo)  = *(const uint4*)&g_mhd_l[si];
    }
    __syncthreads();
    float acc[2][4][4];
    #pragma unroll
    for (int mt=0;mt<2;mt++)
        #pragma unroll
        for (int nt=0;nt<4;nt++)
            #pragma unroll
            for (int j=0;j<4;j++) acc[mt][nt][j]=0.f;
    #pragma unroll
    for (int ks=0;ks<4;ks++){
        uint32_t ah[2][4], al[2][4];
        #pragma unroll
        for (int mt=0;mt<2;mt++){
            uint32_t off = SW128((uint32_t)((wm+mt*16+(lane&15))*128 + ks*32 + (lane>>4)*16));
            LDSM4(ah[mt], sAh + off);
            LDSM4(al[mt], sAl + off);
        }
        uint32_t bh[2][4], bl[2][4];
        #pragma unroll
        for (int p=0;p<2;p++){
            int brow = wn + p*16 + ((lane>>4)&1)*8 + (lane&7);
            uint32_t off = SW128((uint32_t)(brow*128 + ks*32 + ((lane>>3)&1)*16));
            LDSM4(bh[p], sBh + off);
            LDSM4(bl[p], sBl + off);
        }
        #pragma unroll
        for (int mt=0;mt<2;mt++){
            #pragma unroll
            for (int nt=0;nt<4;nt++){
                int p = nt>>1, o = (nt&1)*2;
                MMA_BF16(acc[mt][nt], ah[mt], bh[p][o], bh[p][o+1]);
                MMA_BF16(acc[mt][nt], ah[mt], bl[p][o], bl[p][o+1]);
                MMA_BF16(acc[mt][nt], al[mt], bh[p][o], bh[p][o+1]);
            }
        }
    }
    int gr = lane>>2, gc = (lane&3)*2;
    #pragma unroll
    for (int mt=0;mt<2;mt++){
        #pragma unroll
        for (int nt=0;nt<4;nt++){
            int row = mBase + wm + mt*16 + gr;
            int col = h*64 + wn + nt*8 + gc;
            size_t o0 = (size_t)row*5*Edim + (size_t)g*Edim + col;
            size_t o1 = (size_t)(row+8)*5*Edim + (size_t)g*Edim + col;
            *(float2*)&g_proj[o0] = make_float2(acc[mt][nt][0], acc[mt][nt][1]);
            *(float2*)&g_proj[o1] = make_float2(acc[mt][nt][2], acc[mt][nt][3]);
        }
    }
}

// ---------------- K3b: fused decay lora + parallel vr ----------------
__global__ __launch_bounds__(256) void k_wdecay(const float* __restrict__ wlam,
                                                const float* __restrict__ wA,
                                                const float* __restrict__ wB){
    __shared__ float asm_[64][68];
    __shared__ float wsm[64][68];
    int h = blockIdx.y;
    int m0 = blockIdx.x*64;
    int tid = threadIdx.x;
    {
        int row = tid>>2, q = tid&3;
        const float* v = g_proj + ((size_t)(m0+row)*5+1)*Edim + h*64 + q*16;
        const float* r = g_proj + ((size_t)(m0+row)*5+2)*Edim + h*64 + q*16;
        float s = 0.f;
        #pragma unroll
        for (int j=0;j<4;j++){
            float4 vv = *(const float4*)&v[j*4];
            float4 rr = *(const float4*)&r[j*4];
            s += vv.x*rr.x + vv.y*rr.y + vv.z*rr.z + vv.w*rr.w;
        }
        s += __shfl_xor_sync(0xffffffffu, s, 1);
        s += __shfl_xor_sync(0xffffffffu, s, 2);
        if (q==0) g_vr[(m0+row)*Hdim + h] = s;
    }
    #pragma unroll
    for (int j=0;j<4;j++){
        int f = tid + j*256;
        int row = f>>4, c4 = (f&15)*4;
        *(float4*)&asm_[row][c4] =
            *(const float4*)&g_proj[(size_t)(m0+row)*5*Edim + 3*Edim + h*64 + c4];
        *(float4*)&wsm[row][c4] = *(const float4*)&wA[(size_t)h*4096 + row*64 + c4];
    }
    __syncthreads();
    int tx = tid&15, ty = tid>>4;
    int n0 = tx*4, m0r = ty*4;
    ull acc[4][2];
    #pragma unroll
    for (int i=0;i<4;i++){ acc[i][0]=0ull; acc[i][1]=0ull; }
    #pragma unroll 16
    for (int k=0;k<64;k++){
        ull b01 = *(const ull*)&wsm[k][n0];
        ull b23 = *(const ull*)&wsm[k][n0+2];
        #pragma unroll
        for (int i=0;i<4;i++){
            float a = asm_[m0r+i][k];
            ull a2 = pack2(a, a);
            fma2(acc[i][0], a2, b01);
            fma2(acc[i][1], a2, b23);
        }
    }
    __syncthreads();
    #pragma unroll
    for (int i=0;i<4;i++){
        float2 lo = unpack2(acc[i][0]), hi = unpack2(acc[i][1]);
        *(float4*)&asm_[m0r+i][n0] =
            make_float4(tanhf(lo.x), tanhf(lo.y), tanhf(hi.x), tanhf(hi.y));
        acc[i][0]=0ull; acc[i][1]=0ull;
    }
    #pragma unroll
    for (int j=0;j<4;j++){
        int f = tid + j*256;
        int row = f>>4, c4 = (f&15)*4;
        *(float4*)&wsm[row][c4] = *(const float4*)&wB[(size_t)h*4096 + row*64 + c4];
    }
    __syncthreads();
    #pragma unroll 16
    for (int k=0;k<64;k++){
        ull b01 = *(const ull*)&wsm[k][n0];
        ull b23 = *(const ull*)&wsm[k][n0+2];
        #pragma unroll
        for (int i=0;i<4;i++){
            float a = asm_[m0r+i][k];
            ull a2 = pack2(a, a);
            fma2(acc[i][0], a2, b01);
            fma2(acc[i][1], a2, b23);
        }
    }
    #pragma unroll
    for (int i=0;i<4;i++){
        float2 lo = unpack2(acc[i][0]), hi = unpack2(acc[i][1]);
        float v[4] = {lo.x, lo.y, hi.x, hi.y};
        #pragma unroll
        for (int j=0;j<4;j++)
            v[j] = expf(-expf(v[j] + wlam[h*64 + n0 + j]));
        *(float4*)&g_wdec[(size_t)(m0+m0r+i)*Edim + h*64 + n0] =
            make_float4(v[0],v[1],v[2],v[3]);
    }
}

// ---------------- K4: HMMA bf16-split big GEMM ----------------
#define HS_BUF 16384
#define HS_SMEM (4*HS_BUF + 1024)
__global__ __launch_bounds__(256)
void k_gemm_hmma(const __nv_bfloat16* __restrict__ Ah, const __nv_bfloat16* __restrict__ Al,
                 const __nv_bfloat16* __restrict__ Bh, const __nv_bfloat16* __restrict__ Bl,
                 const float* __restrict__ bias, float* __restrict__ C){
    extern __shared__ char smg[];
    uint32_t dynb = smem_u32(smg);
    uint32_t db = (dynb + 1023u) & ~1023u;
    char* dptr = smg + (db - dynb);
    int tid = threadIdx.x, wid = tid>>5, lane = tid&31;
    int mBase = blockIdx.x*128, nBase = blockIdx.y*128;
    int wm = (wid&1)*64, wn = (wid>>1)*32;
    uint32_t sAh = db, sAl = db + HS_BUF, sBh = db + 2*HS_BUF, sBl = db + 3*HS_BUF;
    float acc[4][4][4];
    #pragma unroll
    for (int mt=0;mt<4;mt++)
        #pragma unroll
        for (int nt=0;nt<4;nt++)
            #pragma unroll
            for (int j=0;j<4;j++) acc[mt][nt][j]=0.f;
    int lrow = tid>>3, lc = tid&7;
    uint4 pa[4], pal[4], pb[4], pbl[4];
    #pragma unroll
    for (int jj=0;jj<4;jj++){
        int row = lrow + jj*32;
        pa[jj]  = *(const uint4*)&Ah[(size_t)(mBase+row)*Edim + lc*8];
        pal[jj] = *(const uint4*)&Al[(size_t)(mBase+row)*Edim + lc*8];
        pb[jj]  = *(const uint4*)&Bh[(size_t)(nBase+row)*Edim + lc*8];
        pbl[jj] = *(const uint4*)&Bl[(size_t)(nBase+row)*Edim + lc*8];
    }
    for (int i=0;i<16;i++){
        #pragma unroll
        for (int jj=0;jj<4;jj++){
            int row = lrow + jj*32;
            uint32_t swo = SW128((uint32_t)(row*128 + lc*16));
            *(uint4*)(dptr + swo)            = pa[jj];
            *(uint4*)(dptr + HS_BUF + swo)   = pal[jj];
            *(uint4*)(dptr + 2*HS_BUF + swo) = pb[jj];
            *(uint4*)(dptr + 3*HS_BUF + swo) = pbl[jj];
        }
        __syncthreads();
        if (i+1 < 16){
            int k0 = (i+1)*64;
            #pragma unroll
            for (int jj=0;jj<4;jj++){
                int row = lrow + jj*32;
                pa[jj]  = *(const uint4*)&Ah[(size_t)(mBase+row)*Edim + k0 + lc*8];
                pal[jj] = *(const uint4*)&Al[(size_t)(mBase+row)*Edim + k0 + lc*8];
                pb[jj]  = *(const uint4*)&Bh[(size_t)(nBase+row)*Edim + k0 + lc*8];
                pbl[jj] = *(const uint4*)&Bl[(size_t)(nBase+row)*Edim + k0 + lc*8];
            }
        }
        #pragma unroll
        for (int ks=0;ks<4;ks++){
            uint32_t ah[4][4], al[4][4];
            #pragma unroll
            for (int mt=0;mt<4;mt++){
                uint32_t off = SW128((uint32_t)((wm+mt*16+(lane&15))*128 + ks*32 + (lane>>4)*16));
                LDSM4(ah[mt], sAh + off);
                LDSM4(al[mt], sAl + off);
            }
            uint32_t bh[2][4], bl[2][4];
            #pragma unroll
            for (int p=0;p<2;p++){
                int brow = wn + p*16 + ((lane>>4)&1)*8 + (lane&7);
                uint32_t off = SW128((uint32_t)(brow*128 + ks*32 + ((lane>>3)&1)*16));
                LDSM4(bh[p], sBh + off);
                LDSM4(bl[p], sBl + off);
            }
            #pragma unroll
            for (int mt=0;mt<4;mt++){
                #pragma unroll
                for (int nt=0;nt<4;nt++){
                    int p = nt>>1, o = (nt&1)*2;
                    MMA_BF16(acc[mt][nt], ah[mt], bh[p][o], bh[p][o+1]);
                    MMA_BF16(acc[mt][nt], ah[mt], bl[p][o], bl[p][o+1]);
                    MMA_BF16(acc[mt][nt], al[mt], bh[p][o], bh[p][o+1]);
                }
            }
        }
        __syncthreads();
    }
    int gr = lane>>2, gc = (lane&3)*2;
    #pragma unroll
    for (int mt=0;mt<4;mt++){
        #pragma unroll
        for (int nt=0;nt<4;nt++){
            int row = mBase + wm + mt*16 + gr;
            int col = nBase + wn + nt*8 + gc;
            float b0 = bias ? bias[col] : 0.f;
            float b1 = bias ? bias[col+1] : 0.f;
            *(float2*)&C[(size_t)row*Edim + col] =
                make_float2(acc[mt][nt][0] + b0, acc[mt][nt][1] + b1);
            *(float2*)&C[(size_t)(row+8)*Edim + col] =
                make_float2(acc[mt][nt][2] + b0, acc[mt][nt][3] + b1);
        }
    }
}

// ---------------- K6a: chunk-local recurrence ----------------
__global__ __launch_bounds__(256) void k_recur1(){
    int unit = blockIdx.x;
    int c = unit & (NC-1);
    int bh = unit >> 4;
    int b = bh >> 4, h = bh & 15;
    int tid = threadIdx.x;
    int row = tid >> 2, q = tid & 3, c0 = q*16;
    __shared__ float sk[CH][64], su[CH][64], sw[CH][64], sv[CH][64], sr[CH][64];
    __shared__ float svr[CH], sout[CH][64], swcum[CH][64];
    ull S2[8];
    #pragma unroll
    for (int j=0;j<8;j++) S2[j] = 0ull;
    float wcumr = 1.f;
    int mbase = b*Tdim + c*CHK;
    float rk[4], ru[4], rw[4], rv[4], rr[4], rvr = 0.f;
    #pragma unroll
    for (int it=0;it<4;it++){
        int idx = tid + it*256; int st = idx>>6, col = idx&63;
        size_t m = (size_t)(mbase + st);
        const float* bp = g_proj + m*5*Edim + h*64 + col;
        rk[it] = bp[0]; rv[it] = bp[Edim]; rr[it] = bp[2*Edim]; ru[it] = bp[4*Edim];
        rw[it] = g_wdec[m*Edim + h*64 + col];
    }
    if (tid < CH) rvr = g_vr[(mbase+tid)*Hdim + h];
    for (int cc=0; cc<CHK/CH; cc++){
        #pragma unroll
        for (int it=0;it<4;it++){
            int idx = tid + it*256; int st = idx>>6, col = idx&63;
            sk[st][col]=rk[it]; su[st][col]=ru[it]; sw[st][col]=rw[it];
            sv[st][col]=rv[it]; sr[st][col]=rr[it];
        }
        if (tid < CH) svr[tid] = rvr;
        __syncthreads();
        if (cc+1 < CHK/CH){
            int t0 = (cc+1)*CH;
            #pragma unroll
            for (int it=0;it<4;it++){
                int idx = tid + it*256; int st = idx>>6, col = idx&63;
                size_t m = (size_t)(mbase + t0 + st);
                const float* bp = g_proj + m*5*Edim + h*64 + col;
                rk[it] = bp[0]; rv[it] = bp[Edim]; rr[it] = bp[2*Edim]; ru[it] = bp[4*Edim];
                rw[it] = g_wdec[m*Edim + h*64 + col];
            }
            if (tid < CH) rvr = g_vr[(mbase+t0+tid)*Hdim + h];
        }
        #pragma unroll
        for (int t=0;t<CH;t++){
            float kc = sk[t][row], wc = sw[t][row], uc = su[t][row], vc = svr[t];
            ull kc2 = pack2(kc, kc), wc2 = pack2(wc, wc);
            const ull* r2 = (const ull*)&sr[t][c0];
            const ull* v2 = (const ull*)&sv[t][c0];
            ull da0=0ull, da1=0ull, da2=0ull, da3=0ull;
            fma2(da0, S2[0], r2[0]); fma2(da1, S2[1], r2[1]);
            fma2(da2, S2[2], r2[2]); fma2(da3, S2[3], r2[3]);
            fma2(da0, S2[4], r2[4]); fma2(da1, S2[5], r2[5]);
            fma2(da2, S2[6], r2[6]); fma2(da3, S2[7], r2[7]);
            float2 p0 = unpack2(da0), p1 = unpack2(da1);
            float2 p2 = unpack2(da2), p3 = unpack2(da3);
            float dot = ((p0.x+p0.y)+(p1.x+p1.y)) + ((p2.x+p2.y)+(p3.x+p3.y));
            dot += __shfl_xor_sync(0xffffffffu, dot, 1);
            dot += __shfl_xor_sync(0xffffffffu, dot, 2);
            if (q==0){
                sout[t][row]  = uc*kc*vc + dot;
                swcum[t][row] = wcumr;
            }
            wcumr *= wc;
            #pragma unroll
            for (int j=0;j<8;j++){
                mul2(S2[j], wc2, S2[j]);
                fma2(S2[j], kc2, v2[j]);
            }
        }
        __syncthreads();
        #pragma unroll
        for (int it=0;it<4;it++){
            int idx = tid + it*256; int st = idx>>6, col = idx&63;
            size_t di = (size_t)(mbase + cc*CH + st)*Edim + h*64 + col;
            g_rwkv[di] = sout[st][col];
            g_wcum[di] = swcum[st][col];
        }
    }
    size_t sb = ((size_t)bh*NC + c)*4096 + row*64 + c0;
    #pragma unroll
    for (int j=0;j<8;j++)
        *(ull*)&g_send[sb + 2*j] = S2[j];
    if (q==0) g_wprod[((size_t)bh*NC + c)*64 + row] = wcumr;
}

// ---------------- K6b: sequential chunk combine ----------------
__global__ __launch_bounds__(256) void k_recur2(){
    int bh = blockIdx.x;
    int tid = threadIdx.x;
    int off = tid*16;
    int d = off >> 6;
    float4 S[4];
    #pragma unroll
    for (int j=0;j<4;j++) S[j] = make_float4(0.f,0.f,0.f,0.f);
    for (int c=0;c<NC;c++){
        size_t sb = ((size_t)bh*NC + c)*4096 + off;
        #pragma unroll
        for (int j=0;j<4;j++)
            *(float4*)&g_sstart[sb + j*4] = S[j];
        float wp = g_wprod[((size_t)bh*NC + c)*64 + d];
        #pragma unroll
        for (int j=0;j<4;j++){
            float4 se = *(const float4*)&g_send[sb + j*4];
            S[j].x = se.x + wp*S[j].x;
            S[j].y = se.y + wp*S[j].y;
            S[j].z = se.z + wp*S[j].z;
            S[j].w = se.w + wp*S[j].w;
        }
    }
}

// ---------------- K6c: cross-chunk correction ----------------
__global__ __launch_bounds__(256) void k_recur3(){
    __shared__ float rsm[64][68];
    __shared__ float ssm[64][68];
    int h = blockIdx.y;
    int m0 = blockIdx.x*64;
    int b = m0 >> 10;
    int c = (m0 & (Tdim-1)) >> 6;
    int bh = b*Hdim + h;
    const float* Sst = g_sstart + ((size_t)bh*NC + c)*4096;
    int tid = threadIdx.x;
    #pragma unroll
    for (int j=0;j<4;j++){
        int f = tid + j*256;
        int row = f>>4, c4 = (f&15)*4;
        *(float4*)&rsm[row][c4] =
            *(const float4*)&g_proj[(size_t)(m0+row)*5*Edim + 2*Edim + h*64 + c4];
        float4 sv = *(const float4*)&Sst[row*64 + c4];
        ssm[c4+0][row] = sv.x; ssm[c4+1][row] = sv.y;
        ssm[c4+2][row] = sv.z; ssm[c4+3][row] = sv.w;
    }
    __syncthreads();
    int tx = tid&15, ty = tid>>4;
    int n0 = tx*4, m0r = ty*4;
    ull acc[4][2];
    #pragma unroll
    for (int i=0;i<4;i++){ acc[i][0]=0ull; acc[i][1]=0ull; }
    #pragma unroll 16
    for (int k=0;k<64;k++){
        ull b01 = *(const ull*)&ssm[k][n0];
        ull b23 = *(const ull*)&ssm[k][n0+2];
        #pragma unroll
        for (int i=0;i<4;i++){
            float a = rsm[m0r+i][k];
            ull a2 = pack2(a, a);
            fma2(acc[i][0], a2, b01);
            fma2(acc[i][1], a2, b23);
        }
    }
    #pragma unroll
    for (int i=0;i<4;i++){
        float2 lo = unpack2(acc[i][0]), hi = unpack2(acc[i][1]);
        size_t di = (size_t)(m0+m0r+i)*Edim + h*64 + n0;
        float4 wc = *(const float4*)&g_wcum[di];
        float4 ov = *(const float4*)&g_rwkv[di];
        ov.x += wc.x*lo.x; ov.y += wc.y*lo.y;
        ov.z += wc.z*hi.x; ov.w += wc.w*hi.y;
        *(float4*)&g_rwkv[di] = ov;
    }
}

// ---------------- K7: GroupNorm * silu(gate) -> bf16 hi/lo ----------------
__global__ __launch_bounds__(256) void k_gn(const float* __restrict__ gamma,
                                            const float* __restrict__ beta){
    int unit = blockIdx.x*8 + (threadIdx.x>>5);
    int lane = threadIdx.x & 31;
    int m = unit>>4, h = unit&15;
    size_t base = (size_t)m*Edim + h*64;
    float v1 = g_rwkv[base + lane];
    float v2 = g_rwkv[base + 32 + lane];
    float s = v1+v2, sq = v1*v1 + v2*v2;
    #pragma unroll
    for (int o=16;o;o>>=1){
        s  += __shfl_xor_sync(0xffffffffu, s, o);
        sq += __shfl_xor_sync(0xffffffffu, sq, o);
    }
    float mean = s*(1.f/64.f);
    float var  = sq*(1.f/64.f) - mean*mean;
    float rstd = rsqrtf(var + 1e-3f);
    #pragma unroll
    for (int half=0; half<2; half++){
        int e = h*64 + half*32 + lane;
        float v = half ? v2 : v1;
        float nv = (v-mean)*rstd*gamma[e] + beta[e];
        float gg = g_gate[(size_t)m*Edim + e];
        float a = nv * (gg/(1.f+expf(-gg)));
        size_t di = (size_t)m*Edim + e;
        __nv_bfloat16 hi = __float2bfloat16(a);
        g_oah[di] = hi;
        g_oal[di] = __float2bfloat16(a - __bfloat162float(hi));
    }
}

extern "C" void kernel_launch(void* const* d_in, const int* in_sizes, int n_in,
                              void* d_out, int out_size) {
    const float* x    = (const float*)d_in[0];
    const float* mu_x = (const float*)d_in[1];
    const float* lam  = (const float*)d_in[2];
    const float* Aw   = (const float*)d_in[3];
    const float* Ab   = (const float*)d_in[4];
    const float* Bw   = (const float*)d_in[5];
    const float* Bb   = (const float*)d_in[6];
    const float* mhd  = (const float*)d_in[7];
    const float* gw   = (const float*)d_in[8];
    const float* wlam = (const float*)d_in[9];
    const float* wA   = (const float*)d_in[10];
    const float* wB   = (const float*)d_in[11];
    const float* gng  = (const float*)d_in[12];
    const float* gnb  = (const float*)d_in[13];
    const float* ow   = (const float*)d_in[14];
    const float* ob   = (const float*)d_in[15];
    float* out = (float*)d_out;

    float *p_gate;
    cudaGetSymbolAddress((void**)&p_gate, g_gate);
    __nv_bfloat16 *p_gah, *p_gal, *p_oah, *p_oal, *p_gwh, *p_gwl, *p_owh, *p_owl;
    cudaGetSymbolAddress((void**)&p_gah, g_gah);
    cudaGetSymbolAddress((void**)&p_gal, g_gal);
    cudaGetSymbolAddress((void**)&p_oah, g_oah);
    cudaGetSymbolAddress((void**)&p_oal, g_oal);
    cudaGetSymbolAddress((void**)&p_gwh, g_gwt_h);
    cudaGetSymbolAddress((void**)&p_gwl, g_gwt_l);
    cudaGetSymbolAddress((void**)&p_owh, g_owt_h);
    cudaGetSymbolAddress((void**)&p_owl, g_owt_l);

    static cudaStream_t s2 = nullptr;
    static cudaEvent_t e_root = nullptr, e_lb = nullptr, e_gate = nullptr, e_wp = nullptr;
    static bool attr_done = false;
    if (!attr_done){
        cudaFuncSetAttribute(k_gemm_hmma,  cudaFuncAttributeMaxDynamicSharedMemorySize, HS_SMEM);
        cudaFuncSetAttribute(k_headgemm,   cudaFuncAttributeMaxDynamicSharedMemorySize, PH_SMEM + 1024);
        cudaFuncSetAttribute(k_loraB_hmma, cudaFuncAttributeMaxDynamicSharedMemorySize, LB_SMEM);
        cudaStreamCreateWithFlags(&s2, cudaStreamNonBlocking);
        cudaEventCreateWithFlags(&e_root, cudaEventDisableTiming);
        cudaEventCreateWithFlags(&e_lb,   cudaEventDisableTiming);
        cudaEventCreateWithFlags(&e_gate, cudaEventDisableTiming);
        cudaEventCreateWithFlags(&e_wp,   cudaEventDisableTiming);
        attr_done = true;
    }

    // fork s2 from the captured origin stream FIRST (capture legality)
    cudaEventRecord(e_root, 0);
    cudaStreamWaitEvent(s2, e_root, 0);

    // weight prep on side stream (independent of x-processing)
    k_wprep<<<dim3(Edim/32, Edim/32, 2), 256, 0, s2>>>(gw, ow);
    k_mhdprep<<<80, 256, 0, s2>>>(mhd);
    cudaEventRecord(e_wp, s2);

    // main chain
    k_bwprep<<<dim3(Edim/256, 6), 256>>>(Bw, lam, Bb);
    k_loraA_part<<<dim3(Mdim/64, 6, KSPLIT), 256>>>(x, mu_x, Aw);
    k_loraA_fin<<<(Mdim*192)/256, 256>>>(Ab);
    k_loraB_hmma<<<dim3(Mdim/128, Edim/128, 6), 256, LB_SMEM>>>(x);
    cudaEventRecord(e_lb, 0);

    // gate GEMM on side stream (after wprep via s2 order, after loraB via e_lb)
    cudaStreamWaitEvent(s2, e_lb, 0);
    k_gemm_hmma<<<dim3(Mdim/128, Edim/128), 256, HS_SMEM, s2>>>(p_gah, p_gal, p_gwh, p_gwl, nullptr, p_gate);
    cudaEventRecord(e_gate, s2);

    cudaStreamWaitEvent(0, e_wp, 0);    // headgemm needs mhdprep
    k_headgemm<<<dim3(Mdim/128, 80), 256, PH_SMEM + 1024>>>(nullptr);
    k_wdecay<<<dim3(Mdim/64, 16), 256>>>(wlam, wA, wB);
    k_recur1<<<Bdim*Hdim*NC, 256>>>();
    k_recur2<<<Bdim*Hdim, 256>>>();
    k_recur3<<<dim3(Mdim/64, Hdim), 256>>>();
    cudaStreamWaitEvent(0, e_gate, 0);
    k_gn<<<(Mdim*Hdim)/8, 256>>>(gng, gnb);
    k_gemm_hmma<<<dim3(Mdim/128, Edim/128), 256, HS_SMEM>>>(p_oah, p_oal, p_owh, p_owl, ob, out);
}

// round 17
// speedup vs baseline: 1.2591x; 1.0803x over previous
#include <cuda_runtime.h>
#include <cuda_bf16.h>
#include <cstdint>

#define Bdim 2
#define Tdim 1024
#define Edim 1024
#define Hdim 16
#define Ddim 64
#define Rdim 32
#define Mdim (Bdim*Tdim)
#define CH 16
#define NC 16
#define CHK (Tdim/NC)
#define KSPLIT 4

typedef unsigned long long ull;

// ---------------- scratch ----------------
__device__ float g_hdnp[(size_t)KSPLIT*Mdim*6*Rdim];
__device__ float g_proj[(size_t)Mdim*5*Edim];
__device__ float g_gate[(size_t)Mdim*Edim];
__device__ float g_wdec[(size_t)Mdim*Edim];
__device__ float g_vr  [(size_t)Mdim*Hdim];
__device__ float g_rwkv[(size_t)Mdim*Edim];
__device__ float g_wcum[(size_t)Mdim*Edim];
__device__ float g_send[(size_t)Bdim*Hdim*NC*4096];
__device__ float g_sstart[(size_t)Bdim*Hdim*NC*4096];
__device__ float g_wprod[(size_t)Bdim*Hdim*NC*64];
__device__ float g_lbb [(size_t)6*Edim];
__device__ __align__(16) __nv_bfloat16 g_zh[(size_t)Mdim*Edim];
__device__ __align__(16) __nv_bfloat16 g_zl[(size_t)Mdim*Edim];
__device__ __align__(16) __nv_bfloat16 g_awth[(size_t)192*Edim];
__device__ __align__(16) __nv_bfloat16 g_awtl[(size_t)192*Edim];
__device__ __align__(16) __nv_bfloat16 g_hdnh[(size_t)Mdim*6*Rdim];
__device__ __align__(16) __nv_bfloat16 g_hdnl[(size_t)Mdim*6*Rdim];
__device__ __align__(16) __nv_bfloat16 g_bwth[(size_t)6*Edim*Rdim];
__device__ __align__(16) __nv_bfloat16 g_bwtl[(size_t)6*Edim*Rdim];
__device__ __align__(16) __nv_bfloat16 g_ddh[(size_t)Mdim*5*Edim];
__device__ __align__(16) __nv_bfloat16 g_ddl[(size_t)Mdim*5*Edim];
__device__ __align__(16) __nv_bfloat16 g_gah[(size_t)Mdim*Edim];
__device__ __align__(16) __nv_bfloat16 g_gal[(size_t)Mdim*Edim];
__device__ __align__(16) __nv_bfloat16 g_oah[(size_t)Mdim*Edim];
__device__ __align__(16) __nv_bfloat16 g_oal[(size_t)Mdim*Edim];
__device__ __align__(16) __nv_bfloat16 g_gwt_h[(size_t)Edim*Edim];
__device__ __align__(16) __nv_bfloat16 g_gwt_l[(size_t)Edim*Edim];
__device__ __align__(16) __nv_bfloat16 g_owt_h[(size_t)Edim*Edim];
__device__ __align__(16) __nv_bfloat16 g_owt_l[(size_t)Edim*Edim];
__device__ __align__(16) __nv_bfloat16 g_mhd_h[(size_t)80*4096];
__device__ __align__(16) __nv_bfloat16 g_mhd_l[(size_t)80*4096];

// ---------------- helpers ----------------
__device__ __forceinline__ ull pack2(float lo, float hi){
    ull r; asm("mov.b64 %0, {%1, %2};" : "=l"(r) : "f"(lo), "f"(hi)); return r;
}
__device__ __forceinline__ void fma2(ull& d, ull a, ull b){
    asm("fma.rn.f32x2 %0, %1, %2, %3;" : "=l"(d) : "l"(a), "l"(b), "l"(d));
}
__device__ __forceinline__ void mul2(ull& d, ull a, ull b){
    asm("mul.rn.f32x2 %0, %1, %2;" : "=l"(d) : "l"(a), "l"(b));
}
__device__ __forceinline__ float2 unpack2(ull v){
    float lo, hi; asm("mov.b64 {%0, %1}, %2;" : "=f"(lo), "=f"(hi) : "l"(v));
    return make_float2(lo, hi);
}
__device__ __forceinline__ uint32_t smem_u32(const void* p){
    uint32_t a; asm("{ .reg .u64 t; cvta.to.shared.u64 t, %1; cvt.u32.u64 %0, t; }" : "=r"(a) : "l"(p));
    return a;
}
#define SW128(o) ((o) ^ ((((uint32_t)(o))>>3) & 0x70u))

#define LDSM4(r, addr) \
    asm volatile("ldmatrix.sync.aligned.m8n8.x4.shared.b16 {%0,%1,%2,%3}, [%4];" \
        : "=r"((r)[0]), "=r"((r)[1]), "=r"((r)[2]), "=r"((r)[3]) : "r"(addr))

#define MMA_BF16(c, a, b0, b1) \
    asm volatile("mma.sync.aligned.m16n8k16.row.col.f32.bf16.bf16.f32 " \
        "{%0,%1,%2,%3}, {%4,%5,%6,%7}, {%8,%9}, {%0,%1,%2,%3};" \
        : "+f"((c)[0]), "+f"((c)[1]), "+f"((c)[2]), "+f"((c)[3]) \
        : "r"((a)[0]), "r"((a)[1]), "r"((a)[2]), "r"((a)[3]), "r"(b0), "r"(b1))

// ---------------- K0: transpose + bf16-split E x E weights ----------------
__global__ __launch_bounds__(256) void k_wprep(const float* __restrict__ gw,
                                               const float* __restrict__ ow){
    __shared__ float tile[32][33];
    const float* src = blockIdx.z ? ow : gw;
    __nv_bfloat16* dh = blockIdx.z ? g_owt_h : g_gwt_h;
    __nv_bfloat16* dl = blockIdx.z ? g_owt_l : g_gwt_l;
    int k0 = blockIdx.x*32, n0 = blockIdx.y*32;
    int tid = threadIdx.x;
    int r = tid>>3, c = (tid&7)*4;
    float4 v4 = *(const float4*)&src[(size_t)(k0+r)*Edim + n0 + c];
    tile[r][c+0] = v4.x; tile[r][c+1] = v4.y;
    tile[r][c+2] = v4.z; tile[r][c+3] = v4.w;
    __syncthreads();
    #pragma unroll
    for (int j=0;j<4;j++){
        float v = tile[c+j][r];
        __nv_bfloat16 hi = __float2bfloat16(v);
        __nv_bfloat16 lo = __float2bfloat16(v - __bfloat162float(hi));
        size_t di = (size_t)(n0+r)*Edim + k0 + c + j;
        dh[di] = hi; dl[di] = lo;
    }
}

// ---------------- K0b: transpose + split per-head weights ----------------
__global__ __launch_bounds__(256) void k_mhdprep(const float* __restrict__ mhd){
    __shared__ float tile[64][68];
    int u = blockIdx.x;
    int tid = threadIdx.x;
    int row = tid>>2, c0 = (tid&3)*16;
    const float* src = mhd + (size_t)u*4096;
    #pragma unroll
    for (int j=0;j<4;j++)
        *(float4*)&tile[row][c0+j*4] = *(const float4*)&src[row*64 + c0 + j*4];
    __syncthreads();
    #pragma unroll
    for (int j=0;j<16;j++){
        float v = tile[c0+j][row];
        __nv_bfloat16 hi = __float2bfloat16(v);
        __nv_bfloat16 lo = __float2bfloat16(v - __bfloat162float(hi));
        size_t di = (size_t)u*4096 + row*64 + c0 + j;
        g_mhd_h[di] = hi; g_mhd_l[di] = lo;
    }
}

// ---------------- K0c: Bw prep ----------------
__global__ __launch_bounds__(256) void k_bwprep(const float* __restrict__ Bw,
                                                const float* __restrict__ lam,
                                                const float* __restrict__ Bb){
    int g = blockIdx.y;
    int e = blockIdx.x*256 + threadIdx.x;
    __nv_bfloat16 hib[32], lob[32];
    #pragma unroll
    for (int r=0;r<32;r++){
        float v = Bw[((size_t)g*Rdim + r)*Edim + e];
        __nv_bfloat16 hi = __float2bfloat16(v);
        hib[r] = hi;
        lob[r] = __float2bfloat16(v - __bfloat162float(hi));
    }
    size_t db = ((size_t)g*Edim + e)*Rdim;
    #pragma unroll
    for (int j=0;j<4;j++){
        *(uint4*)&g_bwth[db + j*8] = *(uint4*)&hib[j*8];
        *(uint4*)&g_bwtl[db + j*8] = *(uint4*)&lob[j*8];
    }
    g_lbb[g*Edim + e] = lam[g*Edim + e] + Bb[g*Edim + e];
}

// ---------------- K0d: Aw[g][k][r] -> awt[g*32+r][k] bf16 hi/lo ----------------
__global__ __launch_bounds__(256) void k_awtprep(const float* __restrict__ Aw){
    __shared__ float tile[32][33];
    int g = blockIdx.y;
    int k0 = blockIdx.x*32;
    int tid = threadIdx.x;
    int r = tid>>3, c = (tid&7)*4;
    float4 v4 = *(const float4*)&Aw[((size_t)g*Edim + k0 + r)*Rdim + c];
    tile[r][c+0] = v4.x; tile[r][c+1] = v4.y;
    tile[r][c+2] = v4.z; tile[r][c+3] = v4.w;
    __syncthreads();
    #pragma unroll
    for (int j=0;j<4;j++){
        float v = tile[r][c+j];       // Aw[g][k0+r][c+j]
        // we need awt[n=g*32+(c+j)][k0+r] — transpose via tile read by column
        (void)v;
    }
    #pragma unroll
    for (int j=0;j<4;j++){
        float v = tile[c+j][r];       // wait: tile[k'][r'] stored as [krow][rcol]
        __nv_bfloat16 hi = __float2bfloat16(v);
        __nv_bfloat16 lo = __float2bfloat16(v - __bfloat162float(hi));
        // tile[a][b] = Aw[g][k0+a][b]; we want awt[g*32+b][k0+a].
        // here a = c+j, b = r:
        size_t di = (size_t)(g*32 + r)*Edim + k0 + c + j;
        g_awth[di] = hi; g_awtl[di] = lo;
    }
}

// ---------------- K0e: z = x + diff*mu_t -> bf16 hi/lo ----------------
__global__ __launch_bounds__(256) void k_zprep(const float* __restrict__ x,
                                               const float* __restrict__ mu_x){
    size_t base = ((size_t)blockIdx.x*256 + threadIdx.x)*4;
    int m = (int)(base >> 10);
    int e = (int)(base & (Edim-1));
    float4 xv = *(const float4*)&x[base];
    float4 lx = make_float4(0.f,0.f,0.f,0.f);
    if (m & (Tdim-1)) lx = *(const float4*)&x[base - Edim];
    float4 mu = *(const float4*)&mu_x[e];
    float z[4];
    { float d=lx.x-xv.x; z[0] = xv.x + d*(xv.x + d*mu.x); }
    { float d=lx.y-xv.y; z[1] = xv.y + d*(xv.y + d*mu.y); }
    { float d=lx.z-xv.z; z[2] = xv.z + d*(xv.z + d*mu.z); }
    { float d=lx.w-xv.w; z[3] = xv.w + d*(xv.w + d*mu.w); }
    __align__(8) __nv_bfloat16 hb[4], lb[4];
    #pragma unroll
    for (int j=0;j<4;j++){
        __nv_bfloat16 hi = __float2bfloat16(z[j]);
        hb[j] = hi;
        lb[j] = __float2bfloat16(z[j] - __bfloat162float(hi));
    }
    *(uint2*)&g_zh[base] = *(uint2*)hb;
    *(uint2*)&g_zl[base] = *(uint2*)lb;
}

// ---------------- K1a: loraA via HMMA split-K: partial[kz] = z @ awt^T ----------------
// grid (Mdim/128, 3, KSPLIT). tile M=128, N=64, K=256.
#define LA_SMEM (49152 + 1024)
__global__ __launch_bounds__(256)
void k_loraA_hmma(const float* __restrict__ unused){
    extern __shared__ char smg[];
    uint32_t dynb = smem_u32(smg);
    uint32_t db = (dynb + 1023u) & ~1023u;
    char* dptr = smg + (db - dynb);
    int tid = threadIdx.x, wid = tid>>5, lane = tid&31;
    int mBase = blockIdx.x*128;
    int nBase = blockIdx.y*64;
    int kz = blockIdx.z;
    int wm = (wid&3)*32, wn = (wid>>2)*32;
    uint32_t sAh = db, sAl = db + 16384, sBh = db + 32768, sBl = db + 40960;
    float acc[2][4][4];
    #pragma unroll
    for (int mt=0;mt<2;mt++)
        #pragma unroll
        for (int nt=0;nt<4;nt++)
            #pragma unroll
            for (int j=0;j<4;j++) acc[mt][nt][j]=0.f;

    for (int it=0; it<4; it++){
        int koff = kz*256 + it*64;
        #pragma unroll
        for (int k=0;k<4;k++){
            int idx = tid + k*256;
            int row = idx>>3, c = idx&7;
            size_t si = (size_t)(mBase+row)*Edim + koff + c*8;
            uint32_t swo = SW128((uint32_t)(row*128 + c*16));
            *(uint4*)(dptr + swo)          = *(const uint4*)&g_zh[si];
            *(uint4*)(dptr + 16384 + swo)  = *(const uint4*)&g_zl[si];
        }
        #pragma unroll
        for (int k=0;k<2;k++){
            int idx = tid + k*256;
            int row = idx>>3, c = idx&7;
            size_t si = (size_t)(nBase+row)*Edim + koff + c*8;
            uint32_t swo = SW128((uint32_t)(row*128 + c*16));
            *(uint4*)(dptr + 32768 + swo)  = *(const uint4*)&g_awth[si];
            *(uint4*)(dptr + 40960 + swo)  = *(const uint4*)&g_awtl[si];
        }
        __syncthreads();
        #pragma unroll
        for (int ks=0;ks<4;ks++){
            uint32_t ah[2][4], al[2][4];
            #pragma unroll
            for (int mt=0;mt<2;mt++){
                uint32_t off = SW128((uint32_t)((wm+mt*16+(lane&15))*128 + ks*32 + (lane>>4)*16));
                LDSM4(ah[mt], sAh + off);
                LDSM4(al[mt], sAl + off);
            }
            uint32_t bh[2][4], bl[2][4];
            #pragma unroll
            for (int p=0;p<2;p++){
                int brow = wn + p*16 + ((lane>>4)&1)*8 + (lane&7);
                uint32_t off = SW128((uint32_t)(brow*128 + ks*32 + ((lane>>3)&1)*16));
                LDSM4(bh[p], sBh + off);
                LDSM4(bl[p], sBl + off);
            }
            #pragma unroll
            for (int mt=0;mt<2;mt++){
                #pragma unroll
                for (int nt=0;nt<4;nt++){
                    int p = nt>>1, o = (nt&1)*2;
                    MMA_BF16(acc[mt][nt], ah[mt], bh[p][o], bh[p][o+1]);
                    MMA_BF16(acc[mt][nt], ah[mt], bl[p][o], bl[p][o+1]);
                    MMA_BF16(acc[mt][nt], al[mt], bh[p][o], bh[p][o+1]);
                }
            }
        }
        __syncthreads();
    }
    int gr = lane>>2, gc = (lane&3)*2;
    float* outp = g_hdnp + (size_t)kz*Mdim*192;
    #pragma unroll
    for (int mt=0;mt<2;mt++){
        #pragma unroll
        for (int nt=0;nt<4;nt++){
            int row = mBase + wm + mt*16 + gr;
            int col = nBase + wn + nt*8 + gc;
            *(float2*)&outp[(size_t)row*192 + col] =
                make_float2(acc[mt][nt][0], acc[mt][nt][1]);
            *(float2*)&outp[(size_t)(row+8)*192 + col] =
                make_float2(acc[mt][nt][2], acc[mt][nt][3]);
        }
    }
}

// ---------------- K1b: loraA finish -> bf16 hi/lo ----------------
__global__ __launch_bounds__(256) void k_loraA_fin(const float* __restrict__ Ab){
    size_t idx = (size_t)blockIdx.x*256 + threadIdx.x;
    int gn = (int)(idx % 192);
    float s = Ab[gn];
    #pragma unroll
    for (int kz=0;kz<KSPLIT;kz++)
        s += g_hdnp[(size_t)kz*Mdim*192 + idx];
    float v = tanhf(s);
    __nv_bfloat16 hi = __float2bfloat16(v);
    g_hdnh[idx] = hi;
    g_hdnl[idx] = __float2bfloat16(v - __bfloat162float(hi));
}

// ---------------- K2: loraB via HMMA + smem-staged ddlerp epilogue ----------------
#define LB_BUF 16384
#define LB_SMEM (128*132*4 + 1024)
__global__ __launch_bounds__(256)
void k_loraB_hmma(const float* __restrict__ x){
    extern __shared__ char smg[];
    uint32_t dynb = smem_u32(smg);
    uint32_t db = (dynb + 1023u) & ~1023u;
    char* dptr = smg + (db - dynb);
    float* accsm = (float*)dptr;
    int tid = threadIdx.x, wid = tid>>5, lane = tid&31;
    int g = blockIdx.z;
    int mBase = blockIdx.x*128, eBase = blockIdx.y*128;
    int wm = (wid&1)*64, wn = (wid>>1)*32;
    uint32_t sAh = db, sAl = db + LB_BUF, sBh = db + 2*LB_BUF, sBl = db + 3*LB_BUF;

    #pragma unroll
    for (int k=0;k<2;k++){
        int idx = tid + k*256;
        int row = idx>>2, c = idx&3;
        uint32_t swo = SW128((uint32_t)(row*128 + c*16));
        size_t ai = ((size_t)(mBase+row)*6 + g)*Rdim + c*8;
        *(uint4*)(dptr + swo)            = *(const uint4*)&g_hdnh[ai];
        *(uint4*)(dptr + LB_BUF + swo)   = *(const uint4*)&g_hdnl[ai];
        size_t bi = ((size_t)g*Edim + eBase+row)*Rdim + c*8;
        *(uint4*)(dptr + 2*LB_BUF + swo) = *(const uint4*)&g_bwth[bi];
        *(uint4*)(dptr + 3*LB_BUF + swo) = *(const uint4*)&g_bwtl[bi];
    }
    __syncthreads();

    float acc[4][4][4];
    #pragma unroll
    for (int mt=0;mt<4;mt++)
        #pragma unroll
        for (int nt=0;nt<4;nt++)
            #pragma unroll
            for (int j=0;j<4;j++) acc[mt][nt][j]=0.f;

    #pragma unroll
    for (int ks=0;ks<2;ks++){
        uint32_t ah[4][4], al[4][4];
        #pragma unroll
        for (int mt=0;mt<4;mt++){
            uint32_t off = SW128((uint32_t)((wm+mt*16+(lane&15))*128 + ks*32 + (lane>>4)*16));
            LDSM4(ah[mt], sAh + off);
            LDSM4(al[mt], sAl + off);
        }
        uint32_t bh[2][4], bl[2][4];
        #pragma unroll
        for (int p=0;p<2;p++){
            int brow = wn + p*16 + ((lane>>4)&1)*8 + (lane&7);
            uint32_t off = SW128((uint32_t)(brow*128 + ks*32 + ((lane>>3)&1)*16));
            LDSM4(bh[p], sBh + off);
            LDSM4(bl[p], sBl + off);
        }
        #pragma unroll
        for (int mt=0;mt<4;mt++){
            #pragma unroll
            for (int nt=0;nt<4;nt++){
                int p = nt>>1, o = (nt&1)*2;
                MMA_BF16(acc[mt][nt], ah[mt], bh[p][o], bh[p][o+1]);
                MMA_BF16(acc[mt][nt], ah[mt], bl[p][o], bl[p][o+1]);
                MMA_BF16(acc[mt][nt], al[mt], bh[p][o], bh[p][o+1]);
            }
        }
    }
    __syncthreads();
    int gr = lane>>2, gc = (lane&3)*2;
    #pragma unroll
    for (int mt=0;mt<4;mt++){
        #pragma unroll
        for (int nt=0;nt<4;nt++){
            int col = wn + nt*8 + gc;
            int r0 = wm + mt*16 + gr;
            *(float2*)&accsm[r0*132 + col]     = make_float2(acc[mt][nt][0], acc[mt][nt][1]);
            *(float2*)&accsm[(r0+8)*132 + col] = make_float2(acc[mt][nt][2], acc[mt][nt][3]);
        }
    }
    __syncthreads();
    #pragma unroll
    for (int j=0;j<16;j++){
        int lin = j*1024 + tid*4;
        int row = lin>>7, col = lin&127;
        float4 a = *(const float4*)&accsm[row*132 + col];
        int gm = mBase + row;
        int ge = eBase + col;
        float4 b = *(const float4*)&g_lbb[g*Edim + ge];
        size_t xi = (size_t)gm*Edim + ge;
        float4 xv = *(const float4*)&x[xi];
        float4 lx = make_float4(0.f,0.f,0.f,0.f);
        if (gm & (Tdim-1)) lx = *(const float4*)&x[xi - Edim];
        float d0 = xv.x + (lx.x - xv.x)*(a.x + b.x);
        float d1 = xv.y + (lx.y - xv.y)*(a.y + b.y);
        float d2 = xv.z + (lx.z - xv.z)*(a.z + b.z);
        float d3 = xv.w + (lx.w - xv.w)*(a.w + b.w);
        __nv_bfloat16 h0=__float2bfloat16(d0), h1=__float2bfloat16(d1);
        __nv_bfloat16 h2=__float2bfloat16(d2), h3=__float2bfloat16(d3);
        __align__(8) __nv_bfloat16 hb[4] = {h0,h1,h2,h3};
        __align__(8) __nv_bfloat16 lb[4] = {
            __float2bfloat16(d0-__bfloat162float(h0)),
            __float2bfloat16(d1-__bfloat162float(h1)),
            __float2bfloat16(d2-__bfloat162float(h2)),
            __float2bfloat16(d3-__bfloat162float(h3))};
        if (g == 5){
            *(uint2*)&g_gah[xi] = *(uint2*)hb;
            *(uint2*)&g_gal[xi] = *(uint2*)lb;
        } else {
            size_t di = ((size_t)gm*5 + g)*Edim + ge;
            *(uint2*)&g_ddh[di] = *(uint2*)hb;
            *(uint2*)&g_ddl[di] = *(uint2*)lb;
        }
    }
}

// ---------------- K3: per-head 64x64 GEMM via HMMA bf16-split ----------------
#define PH_SMEM 49152
__global__ __launch_bounds__(256)
void k_headgemm(const float* __restrict__ unused){
    extern __shared__ char smg[];
    uint32_t dynb = smem_u32(smg);
    uint32_t db = (dynb + 1023u) & ~1023u;
    char* dptr = smg + (db - dynb);
    int tid = threadIdx.x, wid = tid>>5, lane = tid&31;
    int u = blockIdx.y;
    int g = u>>4, h = u&15;
    int mBase = blockIdx.x*128;
    int wm = (wid&3)*32, wn = (wid>>2)*32;
    uint32_t sAh = db, sAl = db + 16384, sBh = db + 32768, sBl = db + 40960;
    #pragma unroll
    for (int k=0;k<4;k++){
        int idx = tid + k*256;
        int row = idx>>3, c = idx&7;
        size_t si = ((size_t)(mBase+row)*5 + g)*Edim + h*64 + c*8;
        uint32_t swo = SW128((uint32_t)(row*128 + c*16));
        *(uint4*)(dptr + swo)          = *(const uint4*)&g_ddh[si];
        *(uint4*)(dptr + 16384 + swo)  = *(const uint4*)&g_ddl[si];
    }
    #pragma unroll
    for (int k=0;k<2;k++){
        int idx = tid + k*256;
        int row = idx>>3, c = idx&7;
        size_t si = (size_t)u*4096 + row*64 + c*8;
        uint32_t swo = SW128((uint32_t)(row*128 + c*16));
        *(uint4*)(dptr + 32768 + swo)  = *(const uint4*)&g_mhd_h[si];
        *(uint4*)(dptr + 40960 + swo)  = *(const uint4*)&g_mhd_l[si];
    }
    __syncthreads();
    float acc[2][4][4];
    #pragma unroll
    for (int mt=0;mt<2;mt++)
        #pragma unroll
        for (int nt=0;nt<4;nt++)
            #pragma unroll
            for (int j=0;j<4;j++) acc[mt][nt][j]=0.f;
    #pragma unroll
    for (int ks=0;ks<4;ks++){
        uint32_t ah[2][4], al[2][4];
        #pragma unroll
        for (int mt=0;mt<2;mt++){
            uint32_t off = SW128((uint32_t)((wm+mt*16+(lane&15))*128 + ks*32 + (lane>>4)*16));
            LDSM4(ah[mt], sAh + off);
            LDSM4(al[mt], sAl + off);
        }
        uint32_t bh[2][4], bl[2][4];
        #pragma unroll
        for (int p=0;p<2;p++){
            int brow = wn + p*16 + ((lane>>4)&1)*8 + (lane&7);
            uint32_t off = SW128((uint32_t)(brow*128 + ks*32 + ((lane>>3)&1)*16));
            LDSM4(bh[p], sBh + off);
            LDSM4(bl[p], sBl + off);
        }
        #pragma unroll
        for (int mt=0;mt<2;mt++){
            #pragma unroll
            for (int nt=0;nt<4;nt++){
                int p = nt>>1, o = (nt&1)*2;
                MMA_BF16(acc[mt][nt], ah[mt], bh[p][o], bh[p][o+1]);
                MMA_BF16(acc[mt][nt], ah[mt], bl[p][o], bl[p][o+1]);
                MMA_BF16(acc[mt][nt], al[mt], bh[p][o], bh[p][o+1]);
            }
        }
    }
    int gr = lane>>2, gc = (lane&3)*2;
    #pragma unroll
    for (int mt=0;mt<2;mt++){
        #pragma unroll
        for (int nt=0;nt<4;nt++){
            int row = mBase + wm + mt*16 + gr;
            int col = h*64 + wn + nt*8 + gc;
            size_t o0 = (size_t)row*5*Edim + (size_t)g*Edim + col;
            size_t o1 = (size_t)(row+8)*5*Edim + (size_t)g*Edim + col;
            *(float2*)&g_proj[o0] = make_float2(acc[mt][nt][0], acc[mt][nt][1]);
            *(float2*)&g_proj[o1] = make_float2(acc[mt][nt][2], acc[mt][nt][3]);
        }
    }
}

// ---------------- K3b: fused decay lora + parallel vr ----------------
__global__ __launch_bounds__(256) void k_wdecay(const float* __restrict__ wlam,
                                                const float* __restrict__ wA,
                                                const float* __restrict__ wB){
    __shared__ float asm_[64][68];
    __shared__ float wsm[64][68];
    int h = blockIdx.y;
    int m0 = blockIdx.x*64;
    int tid = threadIdx.x;
    {
        int row = tid>>2, q = tid&3;
        const float* v = g_proj + ((size_t)(m0+row)*5+1)*Edim + h*64 + q*16;
        const float* r = g_proj + ((size_t)(m0+row)*5+2)*Edim + h*64 + q*16;
        float s = 0.f;
        #pragma unroll
        for (int j=0;j<4;j++){
            float4 vv = *(const float4*)&v[j*4];
            float4 rr = *(const float4*)&r[j*4];
            s += vv.x*rr.x + vv.y*rr.y + vv.z*rr.z + vv.w*rr.w;
        }
        s += __shfl_xor_sync(0xffffffffu, s, 1);
        s += __shfl_xor_sync(0xffffffffu, s, 2);
        if (q==0) g_vr[(m0+row)*Hdim + h] = s;
    }
    #pragma unroll
    for (int j=0;j<4;j++){
        int f = tid + j*256;
        int row = f>>4, c4 = (f&15)*4;
        *(float4*)&asm_[row][c4] =
            *(const float4*)&g_proj[(size_t)(m0+row)*5*Edim + 3*Edim + h*64 + c4];
        *(float4*)&wsm[row][c4] = *(const float4*)&wA[(size_t)h*4096 + row*64 + c4];
    }
    __syncthreads();
    int tx = tid&15, ty = tid>>4;
    int n0 = tx*4, m0r = ty*4;
    ull acc[4][2];
    #pragma unroll
    for (int i=0;i<4;i++){ acc[i][0]=0ull; acc[i][1]=0ull; }
    #pragma unroll 16
    for (int k=0;k<64;k++){
        ull b01 = *(const ull*)&wsm[k][n0];
        ull b23 = *(const ull*)&wsm[k][n0+2];
        #pragma unroll
        for (int i=0;i<4;i++){
            float a = asm_[m0r+i][k];
            ull a2 = pack2(a, a);
            fma2(acc[i][0], a2, b01);
            fma2(acc[i][1], a2, b23);
        }
    }
    __syncthreads();
    #pragma unroll
    for (int i=0;i<4;i++){
        float2 lo = unpack2(acc[i][0]), hi = unpack2(acc[i][1]);
        *(float4*)&asm_[m0r+i][n0] =
            make_float4(tanhf(lo.x), tanhf(lo.y), tanhf(hi.x), tanhf(hi.y));
        acc[i][0]=0ull; acc[i][1]=0ull;
    }
    #pragma unroll
    for (int j=0;j<4;j++){
        int f = tid + j*256;
        int row = f>>4, c4 = (f&15)*4;
        *(float4*)&wsm[row][c4] = *(const float4*)&wB[(size_t)h*4096 + row*64 + c4];
    }
    __syncthreads();
    #pragma unroll 16
    for (int k=0;k<64;k++){
        ull b01 = *(const ull*)&wsm[k][n0];
        ull b23 = *(const ull*)&wsm[k][n0+2];
        #pragma unroll
        for (int i=0;i<4;i++){
            float a = asm_[m0r+i][k];
            ull a2 = pack2(a, a);
            fma2(acc[i][0], a2, b01);
            fma2(acc[i][1], a2, b23);
        }
    }
    #pragma unroll
    for (int i=0;i<4;i++){
        float2 lo = unpack2(acc[i][0]), hi = unpack2(acc[i][1]);
        float v[4] = {lo.x, lo.y, hi.x, hi.y};
        #pragma unroll
        for (int j=0;j<4;j++)
            v[j] = expf(-expf(v[j] + wlam[h*64 + n0 + j]));
        *(float4*)&g_wdec[(size_t)(m0+m0r+i)*Edim + h*64 + n0] =
            make_float4(v[0],v[1],v[2],v[3]);
    }
}

// ---------------- K4: HMMA bf16-split big GEMM ----------------
#define HS_BUF 16384
#define HS_SMEM (4*HS_BUF + 1024)
__global__ __launch_bounds__(256)
void k_gemm_hmma(const __nv_bfloat16* __restrict__ Ah, const __nv_bfloat16* __restrict__ Al,
                 const __nv_bfloat16* __restrict__ Bh, const __nv_bfloat16* __restrict__ Bl,
                 const float* __restrict__ bias, float* __restrict__ C){
    extern __shared__ char smg[];
    uint32_t dynb = smem_u32(smg);
    uint32_t db = (dynb + 1023u) & ~1023u;
    char* dptr = smg + (db - dynb);
    int tid = threadIdx.x, wid = tid>>5, lane = tid&31;
    int mBase = blockIdx.x*128, nBase = blockIdx.y*128;
    int wm = (wid&1)*64, wn = (wid>>1)*32;
    uint32_t sAh = db, sAl = db + HS_BUF, sBh = db + 2*HS_BUF, sBl = db + 3*HS_BUF;
    float acc[4][4][4];
    #pragma unroll
    for (int mt=0;mt<4;mt++)
        #pragma unroll
        for (int nt=0;nt<4;nt++)
            #pragma unroll
            for (int j=0;j<4;j++) acc[mt][nt][j]=0.f;
    int lrow = tid>>3, lc = tid&7;
    uint4 pa[4], pal[4], pb[4], pbl[4];
    #pragma unroll
    for (int jj=0;jj<4;jj++){
        int row = lrow + jj*32;
        pa[jj]  = *(const uint4*)&Ah[(size_t)(mBase+row)*Edim + lc*8];
        pal[jj] = *(const uint4*)&Al[(size_t)(mBase+row)*Edim + lc*8];
        pb[jj]  = *(const uint4*)&Bh[(size_t)(nBase+row)*Edim + lc*8];
        pbl[jj] = *(const uint4*)&Bl[(size_t)(nBase+row)*Edim + lc*8];
    }
    for (int i=0;i<16;i++){
        #pragma unroll
        for (int jj=0;jj<4;jj++){
            int row = lrow + jj*32;
            uint32_t swo = SW128((uint32_t)(row*128 + lc*16));
            *(uint4*)(dptr + swo)            = pa[jj];
            *(uint4*)(dptr + HS_BUF + swo)   = pal[jj];
            *(uint4*)(dptr + 2*HS_BUF + swo) = pb[jj];
            *(uint4*)(dptr + 3*HS_BUF + swo) = pbl[jj];
        }
        __syncthreads();
        if (i+1 < 16){
            int k0 = (i+1)*64;
            #pragma unroll
            for (int jj=0;jj<4;jj++){
                int row = lrow + jj*32;
                pa[jj]  = *(const uint4*)&Ah[(size_t)(mBase+row)*Edim + k0 + lc*8];
                pal[jj] = *(const uint4*)&Al[(size_t)(mBase+row)*Edim + k0 + lc*8];
                pb[jj]  = *(const uint4*)&Bh[(size_t)(nBase+row)*Edim + k0 + lc*8];
                pbl[jj] = *(const uint4*)&Bl[(size_t)(nBase+row)*Edim + k0 + lc*8];
            }
        }
        #pragma unroll
        for (int ks=0;ks<4;ks++){
            uint32_t ah[4][4], al[4][4];
            #pragma unroll
            for (int mt=0;mt<4;mt++){
                uint32_t off = SW128((uint32_t)((wm+mt*16+(lane&15))*128 + ks*32 + (lane>>4)*16));
                LDSM4(ah[mt], sAh + off);
                LDSM4(al[mt], sAl + off);
            }
            uint32_t bh[2][4], bl[2][4];
            #pragma unroll
            for (int p=0;p<2;p++){
                int brow = wn + p*16 + ((lane>>4)&1)*8 + (lane&7);
                uint32_t off = SW128((uint32_t)(brow*128 + ks*32 + ((lane>>3)&1)*16));
                LDSM4(bh[p], sBh + off);
                LDSM4(bl[p], sBl + off);
            }
            #pragma unroll
            for (int mt=0;mt<4;mt++){
                #pragma unroll
                for (int nt=0;nt<4;nt++){
                    int p = nt>>1, o = (nt&1)*2;
                    MMA_BF16(acc[mt][nt], ah[mt], bh[p][o], bh[p][o+1]);
                    MMA_BF16(acc[mt][nt], ah[mt], bl[p][o], bl[p][o+1]);
                    MMA_BF16(acc[mt][nt], al[mt], bh[p][o], bh[p][o+1]);
                }
            }
        }
        __syncthreads();
    }
    int gr = lane>>2, gc = (lane&3)*2;
    #pragma unroll
    for (int mt=0;mt<4;mt++){
        #pragma unroll
        for (int nt=0;nt<4;nt++){
            int row = mBase + wm + mt*16 + gr;
            int col = nBase + wn + nt*8 + gc;
            float b0 = bias ? bias[col] : 0.f;
            float b1 = bias ? bias[col+1] : 0.f;
            *(float2*)&C[(size_t)row*Edim + col] =
                make_float2(acc[mt][nt][0] + b0, acc[mt][nt][1] + b1);
            *(float2*)&C[(size_t)(row+8)*Edim + col] =
                make_float2(acc[mt][nt][2] + b0, acc[mt][nt][3] + b1);
        }
    }
}

// ---------------- K6a: chunk-local recurrence ----------------
__global__ __launch_bounds__(256) void k_recur1(){
    int unit = blockIdx.x;
    int c = unit & (NC-1);
    int bh = unit >> 4;
    int b = bh >> 4, h = bh & 15;
    int tid = threadIdx.x;
    int row = tid >> 2, q = tid & 3, c0 = q*16;
    __shared__ float sk[CH][64], su[CH][64], sw[CH][64], sv[CH][64], sr[CH][64];
    __shared__ float svr[CH], sout[CH][64], swcum[CH][64];
    ull S2[8];
    #pragma unroll
    for (int j=0;j<8;j++) S2[j] = 0ull;
    float wcumr = 1.f;
    int mbase = b*Tdim + c*CHK;
    float rk[4], ru[4], rw[4], rv[4], rr[4], rvr = 0.f;
    #pragma unroll
    for (int it=0;it<4;it++){
        int idx = tid + it*256; int st = idx>>6, col = idx&63;
        size_t m = (size_t)(mbase + st);
        const float* bp = g_proj + m*5*Edim + h*64 + col;
        rk[it] = bp[0]; rv[it] = bp[Edim]; rr[it] = bp[2*Edim]; ru[it] = bp[4*Edim];
        rw[it] = g_wdec[m*Edim + h*64 + col];
    }
    if (tid < CH) rvr = g_vr[(mbase+tid)*Hdim + h];
    for (int cc=0; cc<CHK/CH; cc++){
        #pragma unroll
        for (int it=0;it<4;it++){
            int idx = tid + it*256; int st = idx>>6, col = idx&63;
            sk[st][col]=rk[it]; su[st][col]=ru[it]; sw[st][col]=rw[it];
            sv[st][col]=rv[it]; sr[st][col]=rr[it];
        }
        if (tid < CH) svr[tid] = rvr;
        __syncthreads();
        if (cc+1 < CHK/CH){
            int t0 = (cc+1)*CH;
            #pragma unroll
            for (int it=0;it<4;it++){
                int idx = tid + it*256; int st = idx>>6, col = idx&63;
                size_t m = (size_t)(mbase + t0 + st);
                const float* bp = g_proj + m*5*Edim + h*64 + col;
                rk[it] = bp[0]; rv[it] = bp[Edim]; rr[it] = bp[2*Edim]; ru[it] = bp[4*Edim];
                rw[it] = g_wdec[m*Edim + h*64 + col];
            }
            if (tid < CH) rvr = g_vr[(mbase+t0+tid)*Hdim + h];
        }
        #pragma unroll
        for (int t=0;t<CH;t++){
            float kc = sk[t][row], wc = sw[t][row], uc = su[t][row], vc = svr[t];
            ull kc2 = pack2(kc, kc), wc2 = pack2(wc, wc);
            const ull* r2 = (const ull*)&sr[t][c0];
            const ull* v2 = (const ull*)&sv[t][c0];
            ull da0=0ull, da1=0ull, da2=0ull, da3=0ull;
            fma2(da0, S2[0], r2[0]); fma2(da1, S2[1], r2[1]);
            fma2(da2, S2[2], r2[2]); fma2(da3, S2[3], r2[3]);
            fma2(da0, S2[4], r2[4]); fma2(da1, S2[5], r2[5]);
            fma2(da2, S2[6], r2[6]); fma2(da3, S2[7], r2[7]);
            float2 p0 = unpack2(da0), p1 = unpack2(da1);
            float2 p2 = unpack2(da2), p3 = unpack2(da3);
            float dot = ((p0.x+p0.y)+(p1.x+p1.y)) + ((p2.x+p2.y)+(p3.x+p3.y));
            dot += __shfl_xor_sync(0xffffffffu, dot, 1);
            dot += __shfl_xor_sync(0xffffffffu, dot, 2);
            if (q==0){
                sout[t][row]  = uc*kc*vc + dot;
                swcum[t][row] = wcumr;
            }
            wcumr *= wc;
            #pragma unroll
            for (int j=0;j<8;j++){
                mul2(S2[j], wc2, S2[j]);
                fma2(S2[j], kc2, v2[j]);
            }
        }
        __syncthreads();
        #pragma unroll
        for (int it=0;it<4;it++){
            int idx = tid + it*256; int st = idx>>6, col = idx&63;
            size_t di = (size_t)(mbase + cc*CH + st)*Edim + h*64 + col;
            g_rwkv[di] = sout[st][col];
            g_wcum[di] = swcum[st][col];
        }
    }
    size_t sb = ((size_t)bh*NC + c)*4096 + row*64 + c0;
    #pragma unroll
    for (int j=0;j<8;j++)
        *(ull*)&g_send[sb + 2*j] = S2[j];
    if (q==0) g_wprod[((size_t)bh*NC + c)*64 + row] = wcumr;
}

// ---------------- K6b: sequential chunk combine ----------------
__global__ __launch_bounds__(256) void k_recur2(){
    int bh = blockIdx.x;
    int tid = threadIdx.x;
    int off = tid*16;
    int d = off >> 6;
    float4 S[4];
    #pragma unroll
    for (int j=0;j<4;j++) S[j] = make_float4(0.f,0.f,0.f,0.f);
    for (int c=0;c<NC;c++){
        size_t sb = ((size_t)bh*NC + c)*4096 + off;
        #pragma unroll
        for (int j=0;j<4;j++)
            *(float4*)&g_sstart[sb + j*4] = S[j];
        float wp = g_wprod[((size_t)bh*NC + c)*64 + d];
        #pragma unroll
        for (int j=0;j<4;j++){
            float4 se = *(const float4*)&g_send[sb + j*4];
            S[j].x = se.x + wp*S[j].x;
            S[j].y = se.y + wp*S[j].y;
            S[j].z = se.z + wp*S[j].z;
            S[j].w = se.w + wp*S[j].w;
        }
    }
}

// ---------------- K6c: cross-chunk correction ----------------
__global__ __launch_bounds__(256) void k_recur3(){
    __shared__ float rsm[64][68];
    __shared__ float ssm[64][68];
    int h = blockIdx.y;
    int m0 = blockIdx.x*64;
    int b = m0 >> 10;
    int c = (m0 & (Tdim-1)) >> 6;
    int bh = b*Hdim + h;
    const float* Sst = g_sstart + ((size_t)bh*NC + c)*4096;
    int tid = threadIdx.x;
    #pragma unroll
    for (int j=0;j<4;j++){
        int f = tid + j*256;
        int row = f>>4, c4 = (f&15)*4;
        *(float4*)&rsm[row][c4] =
            *(const float4*)&g_proj[(size_t)(m0+row)*5*Edim + 2*Edim + h*64 + c4];
        float4 sv = *(const float4*)&Sst[row*64 + c4];
        ssm[c4+0][row] = sv.x; ssm[c4+1][row] = sv.y;
        ssm[c4+2][row] = sv.z; ssm[c4+3][row] = sv.w;
    }
    __syncthreads();
    int tx = tid&15, ty = tid>>4;
    int n0 = tx*4, m0r = ty*4;
    ull acc[4][2];
    #pragma unroll
    for (int i=0;i<4;i++){ acc[i][0]=0ull; acc[i][1]=0ull; }
    #pragma unroll 16
    for (int k=0;k<64;k++){
        ull b01 = *(const ull*)&ssm[k][n0];
        ull b23 = *(const ull*)&ssm[k][n0+2];
        #pragma unroll
        for (int i=0;i<4;i++){
            float a = rsm[m0r+i][k];
            ull a2 = pack2(a, a);
            fma2(acc[i][0], a2, b01);
            fma2(acc[i][1], a2, b23);
        }
    }
    #pragma unroll
    for (int i=0;i<4;i++){
        float2 lo = unpack2(acc[i][0]), hi = unpack2(acc[i][1]);
        size_t di = (size_t)(m0+m0r+i)*Edim + h*64 + n0;
        float4 wc = *(const float4*)&g_wcum[di];
        float4 ov = *(const float4*)&g_rwkv[di];
        ov.x += wc.x*lo.x; ov.y += wc.y*lo.y;
        ov.z += wc.z*hi.x; ov.w += wc.w*hi.y;
        *(float4*)&g_rwkv[di] = ov;
    }
}

// ---------------- K7: GroupNorm * silu(gate) -> bf16 hi/lo ----------------
__global__ __launch_bounds__(256) void k_gn(const float* __restrict__ gamma,
                                            const float* __restrict__ beta){
    int unit = blockIdx.x*8 + (threadIdx.x>>5);
    int lane = threadIdx.x & 31;
    int m = unit>>4, h = unit&15;
    size_t base = (size_t)m*Edim + h*64;
    float v1 = g_rwkv[base + lane];
    float v2 = g_rwkv[base + 32 + lane];
    float s = v1+v2, sq = v1*v1 + v2*v2;
    #pragma unroll
    for (int o=16;o;o>>=1){
        s  += __shfl_xor_sync(0xffffffffu, s, o);
        sq += __shfl_xor_sync(0xffffffffu, sq, o);
    }
    float mean = s*(1.f/64.f);
    float var  = sq*(1.f/64.f) - mean*mean;
    float rstd = rsqrtf(var + 1e-3f);
    #pragma unroll
    for (int half=0; half<2; half++){
        int e = h*64 + half*32 + lane;
        float v = half ? v2 : v1;
        float nv = (v-mean)*rstd*gamma[e] + beta[e];
        float gg = g_gate[(size_t)m*Edim + e];
        float a = nv * (gg/(1.f+expf(-gg)));
        size_t di = (size_t)m*Edim + e;
        __nv_bfloat16 hi = __float2bfloat16(a);
        g_oah[di] = hi;
        g_oal[di] = __float2bfloat16(a - __bfloat162float(hi));
    }
}

extern "C" void kernel_launch(void* const* d_in, const int* in_sizes, int n_in,
                              void* d_out, int out_size) {
    const float* x    = (const float*)d_in[0];
    const float* mu_x = (const float*)d_in[1];
    const float* lam  = (const float*)d_in[2];
    const float* Aw   = (const float*)d_in[3];
    const float* Ab   = (const float*)d_in[4];
    const float* Bw   = (const float*)d_in[5];
    const float* Bb   = (const float*)d_in[6];
    const float* mhd  = (const float*)d_in[7];
    const float* gw   = (const float*)d_in[8];
    const float* wlam = (const float*)d_in[9];
    const float* wA   = (const float*)d_in[10];
    const float* wB   = (const float*)d_in[11];
    const float* gng  = (const float*)d_in[12];
    const float* gnb  = (const float*)d_in[13];
    const float* ow   = (const float*)d_in[14];
    const float* ob   = (const float*)d_in[15];
    float* out = (float*)d_out;

    float *p_gate;
    cudaGetSymbolAddress((void**)&p_gate, g_gate);
    __nv_bfloat16 *p_gah, *p_gal, *p_oah, *p_oal, *p_gwh, *p_gwl, *p_owh, *p_owl;
    cudaGetSymbolAddress((void**)&p_gah, g_gah);
    cudaGetSymbolAddress((void**)&p_gal, g_gal);
    cudaGetSymbolAddress((void**)&p_oah, g_oah);
    cudaGetSymbolAddress((void**)&p_oal, g_oal);
    cudaGetSymbolAddress((void**)&p_gwh, g_gwt_h);
    cudaGetSymbolAddress((void**)&p_gwl, g_gwt_l);
    cudaGetSymbolAddress((void**)&p_owh, g_owt_h);
    cudaGetSymbolAddress((void**)&p_owl, g_owt_l);

    static cudaStream_t s2 = nullptr;
    static cudaEvent_t e_root = nullptr, e_lb = nullptr, e_gate = nullptr, e_wp = nullptr;
    static bool attr_done = false;
    if (!attr_done){
        cudaFuncSetAttribute(k_gemm_hmma,  cudaFuncAttributeMaxDynamicSharedMemorySize, HS_SMEM);
        cudaFuncSetAttribute(k_headgemm,   cudaFuncAttributeMaxDynamicSharedMemorySize, PH_SMEM + 1024);
        cudaFuncSetAttribute(k_loraB_hmma, cudaFuncAttributeMaxDynamicSharedMemorySize, LB_SMEM);
        cudaFuncSetAttribute(k_loraA_hmma, cudaFuncAttributeMaxDynamicSharedMemorySize, LA_SMEM);
        cudaStreamCreateWithFlags(&s2, cudaStreamNonBlocking);
        cudaEventCreateWithFlags(&e_root, cudaEventDisableTiming);
        cudaEventCreateWithFlags(&e_lb,   cudaEventDisableTiming);
        cudaEventCreateWithFlags(&e_gate, cudaEventDisableTiming);
        cudaEventCreateWithFlags(&e_wp,   cudaEventDisableTiming);
        attr_done = true;
    }

    // fork s2 from the captured origin stream FIRST (capture legality)
    cudaEventRecord(e_root, 0);
    cudaStreamWaitEvent(s2, e_root, 0);

    // weight prep on side stream
    k_wprep<<<dim3(Edim/32, Edim/32, 2), 256, 0, s2>>>(gw, ow);
    k_mhdprep<<<80, 256, 0, s2>>>(mhd);
    cudaEventRecord(e_wp, s2);

    // main chain
    k_zprep<<<(Mdim*Edim)/1024, 256>>>(x, mu_x);
    k_awtprep<<<dim3(Edim/32, 6), 256>>>(Aw);
    k_bwprep<<<dim3(Edim/256, 6), 256>>>(Bw, lam, Bb);
    k_loraA_hmma<<<dim3(Mdim/128, 3, KSPLIT), 256, LA_SMEM>>>(nullptr);
    k_loraA_fin<<<(Mdim*192)/256, 256>>>(Ab);
    k_loraB_hmma<<<dim3(Mdim/128, Edim/128, 6), 256, LB_SMEM>>>(x);
    cudaEventRecord(e_lb, 0);

    // gate GEMM on side stream
    cudaStreamWaitEvent(s2, e_lb, 0);
    k_gemm_hmma<<<dim3(Mdim/128, Edim/128), 256, HS_SMEM, s2>>>(p_gah, p_gal, p_gwh, p_gwl, nullptr, p_gate);
    cudaEventRecord(e_gate, s2);

    cudaStreamWaitEvent(0, e_wp, 0);
    k_headgemm<<<dim3(Mdim/128, 80), 256, PH_SMEM + 1024>>>(nullptr);
    k_wdecay<<<dim3(Mdim/64, 16), 256>>>(wlam, wA, wB);
    k_recur1<<<Bdim*Hdim*NC, 256>>>();
    k_recur2<<<Bdim*Hdim, 256>>>();
    k_recur3<<<dim3(Mdim/64, Hdim), 256>>>();
    cudaStreamWaitEvent(0, e_gate, 0);
    k_gn<<<(Mdim*Hdim)/8, 256>>>(gng, gnb);
    k_gemm_hmma<<<dim3(Mdim/128, Edim/128), 256, HS_SMEM>>>(p_oah, p_oal, p_owh, p_owl, ob, out);
}